// round 1
// baseline (speedup 1.0000x reference)
#include <cuda_runtime.h>
#include <math.h>

#define B_   4
#define S_   2048
#define D_   1024
#define H_   16
#define DK_  64
#define M_   (B_ * S_)        /* 8192 rows of tokens */
#define N3_  (3 * D_)         /* 3072: q|k|v concatenated */

/* Scratch: static device arrays (no allocations allowed). 96MB + 32MB. */
__device__ float g_qkv[(size_t)M_ * N3_];
__device__ float g_att[(size_t)M_ * D_];

/* ---------------------------------------------------------------------------
 * NT SGEMM: C[M, Ntot] = A[M,K] @ Bcat[Ntot,K]^T
 * Bcat is up to three stacked (1024 x K) weight matrices (nn.Linear layout).
 * 128x128 block tile, BK=8, 8x8 per-thread microtile, 256 threads.
 * All dims divide evenly (M=8192, Ntot in {3072,1024}, K=1024) -> no bounds.
 * ------------------------------------------------------------------------- */
__global__ __launch_bounds__(256, 2)
void sgemm_nt(const float* __restrict__ A,
              const float* __restrict__ B0,
              const float* __restrict__ B1,
              const float* __restrict__ B2,
              float* __restrict__ C,
              int K, int Ntot)
{
    const int BM = 128, BN = 128, BK = 8, TM = 8, TN = 8;
    __shared__ float As[BK][BM];
    __shared__ float Bs[BK][BN];

    const int tid  = threadIdx.x;        /* 0..255 */
    const int brow = blockIdx.y * BM;
    const int bcol = blockIdx.x * BN;

    /* select which stacked weight matrix this column-block lives in */
    const int mi = bcol >> 10;           /* bcol / 1024 */
    const float* __restrict__ Bmat = (mi == 0) ? B0 : ((mi == 1) ? B1 : B2);
    const int bcolLocal = bcol & 1023;

    /* gmem load mapping: each thread fetches one float4 of A and one of B */
    const int lrow = tid >> 1;           /* 0..127 */
    const int lcol = (tid & 1) * 4;      /* 0 or 4 */

    const int tx = tid & 15;             /* 0..15 */
    const int ty = tid >> 4;             /* 0..15 */

    float acc[TM][TN];
    #pragma unroll
    for (int i = 0; i < TM; i++)
        #pragma unroll
        for (int j = 0; j < TN; j++)
            acc[i][j] = 0.0f;

    for (int k0 = 0; k0 < K; k0 += BK) {
        float4 av = *(const float4*)&A   [(size_t)(brow + lrow)      * K + k0 + lcol];
        float4 bv = *(const float4*)&Bmat[(size_t)(bcolLocal + lrow) * K + k0 + lcol];

        __syncthreads();   /* previous iteration's compute done before overwrite */
        As[lcol + 0][lrow] = av.x;
        As[lcol + 1][lrow] = av.y;
        As[lcol + 2][lrow] = av.z;
        As[lcol + 3][lrow] = av.w;
        Bs[lcol + 0][lrow] = bv.x;
        Bs[lcol + 1][lrow] = bv.y;
        Bs[lcol + 2][lrow] = bv.z;
        Bs[lcol + 3][lrow] = bv.w;
        __syncthreads();

        #pragma unroll
        for (int kk = 0; kk < BK; kk++) {
            float a[TM], b[TN];
            *(float4*)&a[0] = *(const float4*)&As[kk][ty * TM];
            *(float4*)&a[4] = *(const float4*)&As[kk][ty * TM + 4];
            *(float4*)&b[0] = *(const float4*)&Bs[kk][tx * TN];
            *(float4*)&b[4] = *(const float4*)&Bs[kk][tx * TN + 4];
            #pragma unroll
            for (int i = 0; i < TM; i++)
                #pragma unroll
                for (int j = 0; j < TN; j++)
                    acc[i][j] = fmaf(a[i], b[j], acc[i][j]);
        }
    }

    #pragma unroll
    for (int i = 0; i < TM; i++) {
        const size_t row = (size_t)(brow + ty * TM + i);
        float* cp = &C[row * Ntot + bcol + tx * TN];
        *(float4*)(cp + 0) = make_float4(acc[i][0], acc[i][1], acc[i][2], acc[i][3]);
        *(float4*)(cp + 4) = make_float4(acc[i][4], acc[i][5], acc[i][6], acc[i][7]);
    }
}

/* ---------------------------------------------------------------------------
 * Flash attention, fp32. One query row per thread.
 * Block: 256 threads = 256 query rows. Key/value tile: 128 rows.
 * smem: K tile (32KB) + V tile (32KB) + per-thread score rows (129-padded,
 * 132KB) = 193KB dynamic.
 * grid: (S/256 = 8, B*H = 64)
 * ------------------------------------------------------------------------- */
#define TQ_  256
#define TK_  128
#define ATTN_SMEM_FLOATS (TK_ * DK_ * 2 + TQ_ * (TK_ + 1))

__global__ __launch_bounds__(TQ_, 1)
void attn_kernel(float* __restrict__ out)
{
    extern __shared__ float sm[];
    float* Ks  = sm;                       /* [TK_][DK_]     */
    float* Vs  = Ks + TK_ * DK_;           /* [TK_][DK_]     */
    float* Ssc = Vs + TK_ * DK_;           /* [TQ_][TK_+1]   */

    const int t  = threadIdx.x;
    const int bh = blockIdx.y;
    const int b  = bh >> 4;                /* / H_ */
    const int h  = bh & 15;
    const int row = blockIdx.x * TQ_ + t;  /* query index in sequence */

    const float* __restrict__ qkv = g_qkv;
    const size_t base = (size_t)(b * S_) * N3_;   /* this batch's rows */

    /* load my query row into registers */
    float q[DK_];
    {
        const float* qp = qkv + base + (size_t)row * N3_ + h * DK_;
        #pragma unroll
        for (int d = 0; d < DK_; d += 4) {
            float4 v = *(const float4*)(qp + d);
            q[d] = v.x; q[d+1] = v.y; q[d+2] = v.z; q[d+3] = v.w;
        }
    }

    float O[DK_];
    #pragma unroll
    for (int d = 0; d < DK_; d++) O[d] = 0.0f;
    float m = -1e30f, l = 0.0f;
    const float scale = 0.125f;            /* 1/sqrt(64) */

    float* srow = &Ssc[t * (TK_ + 1)];

    for (int k0 = 0; k0 < S_; k0 += TK_) {
        __syncthreads();  /* previous tile fully consumed before overwrite */

        /* cooperative load of K and V tiles (float4, coalesced per row) */
        for (int idx = t; idx < TK_ * (DK_ / 4); idx += TQ_) {
            const int r  = idx >> 4;          /* / (DK_/4) */
            const int c4 = (idx & 15) * 4;
            const float* kp = qkv + base + (size_t)(k0 + r) * N3_ + D_     + h * DK_ + c4;
            const float* vp = qkv + base + (size_t)(k0 + r) * N3_ + 2 * D_ + h * DK_ + c4;
            *(float4*)&Ks[r * DK_ + c4] = *(const float4*)kp;
            *(float4*)&Vs[r * DK_ + c4] = *(const float4*)vp;
        }
        __syncthreads();

        /* scores for my row vs this key tile */
        float tmax = -1e30f;
        for (int j = 0; j < TK_; j++) {
            float s0 = 0.f, s1 = 0.f, s2 = 0.f, s3 = 0.f;
            const float* kr = &Ks[j * DK_];
            #pragma unroll
            for (int d = 0; d < DK_; d += 4) {
                float4 k4 = *(const float4*)(kr + d);   /* warp-broadcast */
                s0 = fmaf(q[d    ], k4.x, s0);
                s1 = fmaf(q[d + 1], k4.y, s1);
                s2 = fmaf(q[d + 2], k4.z, s2);
                s3 = fmaf(q[d + 3], k4.w, s3);
            }
            float s = ((s0 + s1) + (s2 + s3)) * scale;
            srow[j] = s;
            tmax = fmaxf(tmax, s);
        }

        /* online softmax rescale */
        const float mnew = fmaxf(m, tmax);
        const float corr = __expf(m - mnew);
        l *= corr;
        #pragma unroll
        for (int d = 0; d < DK_; d++) O[d] *= corr;

        /* accumulate P @ V */
        for (int j = 0; j < TK_; j++) {
            const float p = __expf(srow[j] - mnew);
            l += p;
            const float* vr = &Vs[j * DK_];
            #pragma unroll
            for (int d = 0; d < DK_; d += 4) {
                float4 v4 = *(const float4*)(vr + d);   /* warp-broadcast */
                O[d    ] = fmaf(p, v4.x, O[d    ]);
                O[d + 1] = fmaf(p, v4.y, O[d + 1]);
                O[d + 2] = fmaf(p, v4.z, O[d + 2]);
                O[d + 3] = fmaf(p, v4.w, O[d + 3]);
            }
        }
        m = mnew;
    }

    const float inv = 1.0f / l;
    float* op = out + (size_t)(b * S_ + row) * D_ + h * DK_;
    #pragma unroll
    for (int d = 0; d < DK_; d += 4) {
        *(float4*)(op + d) = make_float4(O[d] * inv, O[d+1] * inv,
                                         O[d+2] * inv, O[d+3] * inv);
    }
}

/* --------------------------------------------------------------------------- */
extern "C" void kernel_launch(void* const* d_in, const int* in_sizes, int n_in,
                              void* d_out, int out_size)
{
    const float* x   = (const float*)d_in[0];
    const float* W_q = (const float*)d_in[1];
    const float* W_k = (const float*)d_in[2];
    const float* W_v = (const float*)d_in[3];
    const float* W_o = (const float*)d_in[4];
    float* out = (float*)d_out;

    float* qkv_ptr = nullptr;
    float* att_ptr = nullptr;
    cudaGetSymbolAddress((void**)&qkv_ptr, g_qkv);
    cudaGetSymbolAddress((void**)&att_ptr, g_att);

    /* allow >48KB dynamic smem for the attention kernel (idempotent) */
    cudaFuncSetAttribute(attn_kernel,
                         cudaFuncAttributeMaxDynamicSharedMemorySize,
                         ATTN_SMEM_FLOATS * (int)sizeof(float));

    /* 1) fused QKV projection: g_qkv[8192, 3072] = x @ [Wq|Wk|Wv]^T */
    {
        dim3 grid(N3_ / 128, M_ / 128);
        sgemm_nt<<<grid, 256>>>(x, W_q, W_k, W_v, qkv_ptr, D_, N3_);
    }

    /* 2) flash attention -> g_att[8192, 1024] (heads re-concatenated) */
    {
        dim3 grid(S_ / TQ_, B_ * H_);
        attn_kernel<<<grid, TQ_, ATTN_SMEM_FLOATS * sizeof(float)>>>(att_ptr);
    }

    /* 3) output projection: out = g_att @ W_out^T */
    {
        dim3 grid(D_ / 128, M_ / 128);
        sgemm_nt<<<grid, 256>>>(att_ptr, W_o, W_o, W_o, out, D_, D_);
    }
}

// round 3
// speedup vs baseline: 2.2358x; 2.2358x over previous
#include <cuda_runtime.h>
#include <math.h>
#include <stdint.h>

#define B_   4
#define S_   2048
#define D_   1024
#define H_   16
#define DK_  64
#define M_   (B_ * S_)        /* 8192 token rows */
#define N3_  (3 * D_)         /* 3072 */

/* Static scratch (no allocations allowed). */
__device__ float g_qkv[(size_t)M_ * N3_];
__device__ float g_att[(size_t)M_ * D_];

/* ===================================================================
 * tf32 mma.sync NT GEMM: C[M, Ntot] = A[M,1024] @ Bcat[Ntot,1024]^T
 *
 * Block: 128x128, K-chunk 32. 256 threads = 8 warps in 4(M) x 2(N).
 * Warp tile 32x64 = 2(M) x 8(N) mma.m16n8k8 tiles.
 * smem: [buf][op][128][36] uint32 (tf32 bits), padded row stride 36:
 *   - STS float4 along k: conflict-free
 *   - fragment LDS: bank = 4*(lane>>2) + (lane&3) = lane  -> conflict-free
 * Double-buffered with register prefetch of the next gmem chunk.
 * All dims divide evenly -> no bounds checks.
 * =================================================================== */
#define GBM 128
#define GBN 128
#define GKB 32
#define NCHUNK (1024 / GKB)        /* 32 */
#define ROWPAD 36                  /* 32 k-floats + 4 pad */
#define OPSTRIDE (128 * ROWPAD)    /* uint32s per operand tile */
#define BUFSTRIDE (2 * OPSTRIDE)
#define GEMM_SMEM (2 * BUFSTRIDE * 4)   /* 73728 bytes */

__device__ __forceinline__ uint32_t f2tf32(float f) {
    uint32_t u;
    asm("cvt.rna.tf32.f32 %0, %1;" : "=r"(u) : "f"(f));
    return u;
}

__device__ __forceinline__ void mma16n8k8(float* d, const uint32_t* a,
                                          uint32_t b0, uint32_t b1) {
    asm volatile(
        "mma.sync.aligned.m16n8k8.row.col.f32.tf32.tf32.f32 "
        "{%0,%1,%2,%3}, {%4,%5,%6,%7}, {%8,%9}, {%0,%1,%2,%3};"
        : "+f"(d[0]), "+f"(d[1]), "+f"(d[2]), "+f"(d[3])
        : "r"(a[0]), "r"(a[1]), "r"(a[2]), "r"(a[3]), "r"(b0), "r"(b1));
}

__global__ __launch_bounds__(256, 2)
void gemm_mma(const float* __restrict__ A,
              const float* __restrict__ B0,
              const float* __restrict__ B1,
              const float* __restrict__ B2,
              float* __restrict__ C, int Ntot)
{
    extern __shared__ uint32_t smu[];
    const int tid  = threadIdx.x;
    const int wid  = tid >> 5;
    const int lane = tid & 31;
    const int g    = lane >> 2;        /* group id 0..7  */
    const int t    = lane & 3;         /* thread in group */
    const int wm   = wid & 3;          /* warp M 0..3 */
    const int wn   = wid >> 2;         /* warp N 0..1 */

    const int brow = blockIdx.y * GBM;
    const int bcol = blockIdx.x * GBN;
    const int mi   = bcol >> 10;
    const float* __restrict__ Bw = (mi == 0) ? B0 : ((mi == 1) ? B1 : B2);
    const int bcl  = bcol & 1023;
    const int K = 1024;

    /* gmem fetch mapping: slot = tid + i*256; row = slot>>3, kq = (slot&7)*4 */
    const int frow = tid >> 3;         /* base row for i=0: 0..31 */
    const int fkq  = (tid & 7) * 4;

    float acc[2][8][4];
    #pragma unroll
    for (int mt = 0; mt < 2; mt++)
        #pragma unroll
        for (int nt = 0; nt < 8; nt++)
            #pragma unroll
            for (int j = 0; j < 4; j++)
                acc[mt][nt][j] = 0.0f;

    float4 pa[4], pb[4];

    /* prefetch chunk 0 */
    #pragma unroll
    for (int i = 0; i < 4; i++) {
        const int r = frow + i * 32;
        pa[i] = *(const float4*)&A [(size_t)(brow + r) * K + fkq];
        pb[i] = *(const float4*)&Bw[(size_t)(bcl  + r) * K + fkq];
    }
    /* store chunk 0 */
    #pragma unroll
    for (int i = 0; i < 4; i++) {
        const int r = frow + i * 32;
        uint32_t* as = &smu[0 * OPSTRIDE + r * ROWPAD + fkq];
        uint32_t* bs = &smu[1 * OPSTRIDE + r * ROWPAD + fkq];
        as[0] = f2tf32(pa[i].x); as[1] = f2tf32(pa[i].y);
        as[2] = f2tf32(pa[i].z); as[3] = f2tf32(pa[i].w);
        bs[0] = f2tf32(pb[i].x); bs[1] = f2tf32(pb[i].y);
        bs[2] = f2tf32(pb[i].z); bs[3] = f2tf32(pb[i].w);
    }
    __syncthreads();

    for (int c = 0; c < NCHUNK; c++) {
        const int buf = c & 1;
        const uint32_t* As = &smu[buf * BUFSTRIDE];
        const uint32_t* Bs = &smu[buf * BUFSTRIDE + OPSTRIDE];

        /* prefetch next chunk into registers */
        if (c + 1 < NCHUNK) {
            const int k0 = (c + 1) * GKB;
            #pragma unroll
            for (int i = 0; i < 4; i++) {
                const int r = frow + i * 32;
                pa[i] = *(const float4*)&A [(size_t)(brow + r) * K + k0 + fkq];
                pb[i] = *(const float4*)&Bw[(size_t)(bcl  + r) * K + k0 + fkq];
            }
        }

        /* compute on current buffer */
        #pragma unroll
        for (int kk = 0; kk < GKB; kk += 8) {
            uint32_t afr[2][4];
            #pragma unroll
            for (int mt = 0; mt < 2; mt++) {
                const int r0 = wm * 32 + mt * 16 + g;
                afr[mt][0] = As[ r0      * ROWPAD + kk + t];
                afr[mt][1] = As[(r0 + 8) * ROWPAD + kk + t];
                afr[mt][2] = As[ r0      * ROWPAD + kk + t + 4];
                afr[mt][3] = As[(r0 + 8) * ROWPAD + kk + t + 4];
            }
            #pragma unroll
            for (int nt = 0; nt < 8; nt++) {
                const int n0 = wn * 64 + nt * 8 + g;
                const uint32_t b0 = Bs[n0 * ROWPAD + kk + t];
                const uint32_t b1 = Bs[n0 * ROWPAD + kk + t + 4];
                mma16n8k8(acc[0][nt], afr[0], b0, b1);
                mma16n8k8(acc[1][nt], afr[1], b0, b1);
            }
        }

        if (c + 1 < NCHUNK) {
            __syncthreads();    /* everyone done reading buf^1 (chunk c-1) */
            const int nbuf = (c + 1) & 1;
            #pragma unroll
            for (int i = 0; i < 4; i++) {
                const int r = frow + i * 32;
                uint32_t* as = &smu[nbuf * BUFSTRIDE + r * ROWPAD + fkq];
                uint32_t* bs = &smu[nbuf * BUFSTRIDE + OPSTRIDE + r * ROWPAD + fkq];
                as[0] = f2tf32(pa[i].x); as[1] = f2tf32(pa[i].y);
                as[2] = f2tf32(pa[i].z); as[3] = f2tf32(pa[i].w);
                bs[0] = f2tf32(pb[i].x); bs[1] = f2tf32(pb[i].y);
                bs[2] = f2tf32(pb[i].z); bs[3] = f2tf32(pb[i].w);
            }
            __syncthreads();
        }
    }

    /* epilogue: c0,c1 -> (row, 2t), (row, 2t+1); c2,c3 -> row+8 */
    #pragma unroll
    for (int mt = 0; mt < 2; mt++) {
        const int row = brow + wm * 32 + mt * 16 + g;
        #pragma unroll
        for (int nt = 0; nt < 8; nt++) {
            const int col = bcol + wn * 64 + nt * 8 + 2 * t;
            float* cp0 = &C[(size_t)row * Ntot + col];
            float* cp1 = &C[(size_t)(row + 8) * Ntot + col];
            *(float2*)cp0 = make_float2(acc[mt][nt][0], acc[mt][nt][1]);
            *(float2*)cp1 = make_float2(acc[mt][nt][2], acc[mt][nt][3]);
        }
    }
}

/* ===================================================================
 * Flash attention, fp32 (unchanged — next round's target).
 * =================================================================== */
#define TQ_  256
#define TK_  128
#define ATTN_SMEM_FLOATS (TK_ * DK_ * 2 + TQ_ * (TK_ + 1))

__global__ __launch_bounds__(TQ_, 1)
void attn_kernel(float* __restrict__ out)
{
    extern __shared__ float smf[];
    float* Ks  = smf;
    float* Vs  = Ks + TK_ * DK_;
    float* Ssc = Vs + TK_ * DK_;

    const int t  = threadIdx.x;
    const int bh = blockIdx.y;
    const int b  = bh >> 4;
    const int h  = bh & 15;
    const int row = blockIdx.x * TQ_ + t;

    const float* __restrict__ qkv = g_qkv;
    const size_t base = (size_t)(b * S_) * N3_;

    float q[DK_];
    {
        const float* qp = qkv + base + (size_t)row * N3_ + h * DK_;
        #pragma unroll
        for (int d = 0; d < DK_; d += 4) {
            float4 v = *(const float4*)(qp + d);
            q[d] = v.x; q[d + 1] = v.y; q[d + 2] = v.z; q[d + 3] = v.w;
        }
    }

    float O[DK_];
    #pragma unroll
    for (int d = 0; d < DK_; d++) O[d] = 0.0f;
    float m = -1e30f, l = 0.0f;
    const float scale = 0.125f;

    float* srow = &Ssc[t * (TK_ + 1)];

    for (int k0 = 0; k0 < S_; k0 += TK_) {
        __syncthreads();
        for (int idx = t; idx < TK_ * (DK_ / 4); idx += TQ_) {
            const int r  = idx >> 4;
            const int c4 = (idx & 15) * 4;
            const float* kp = qkv + base + (size_t)(k0 + r) * N3_ + D_     + h * DK_ + c4;
            const float* vp = qkv + base + (size_t)(k0 + r) * N3_ + 2 * D_ + h * DK_ + c4;
            *(float4*)&Ks[r * DK_ + c4] = *(const float4*)kp;
            *(float4*)&Vs[r * DK_ + c4] = *(const float4*)vp;
        }
        __syncthreads();

        float tmax = -1e30f;
        for (int j = 0; j < TK_; j++) {
            float s0 = 0.f, s1 = 0.f, s2 = 0.f, s3 = 0.f;
            const float* kr = &Ks[j * DK_];
            #pragma unroll
            for (int d = 0; d < DK_; d += 4) {
                float4 k4 = *(const float4*)(kr + d);
                s0 = fmaf(q[d    ], k4.x, s0);
                s1 = fmaf(q[d + 1], k4.y, s1);
                s2 = fmaf(q[d + 2], k4.z, s2);
                s3 = fmaf(q[d + 3], k4.w, s3);
            }
            float s = ((s0 + s1) + (s2 + s3)) * scale;
            srow[j] = s;
            tmax = fmaxf(tmax, s);
        }

        const float mnew = fmaxf(m, tmax);
        const float corr = __expf(m - mnew);
        l *= corr;
        #pragma unroll
        for (int d = 0; d < DK_; d++) O[d] *= corr;

        for (int j = 0; j < TK_; j++) {
            const float p = __expf(srow[j] - mnew);
            l += p;
            const float* vr = &Vs[j * DK_];
            #pragma unroll
            for (int d = 0; d < DK_; d += 4) {
                float4 v4 = *(const float4*)(vr + d);
                O[d    ] = fmaf(p, v4.x, O[d    ]);
                O[d + 1] = fmaf(p, v4.y, O[d + 1]);
                O[d + 2] = fmaf(p, v4.z, O[d + 2]);
                O[d + 3] = fmaf(p, v4.w, O[d + 3]);
            }
        }
        m = mnew;
    }

    const float inv = 1.0f / l;
    float* op = out + (size_t)(b * S_ + row) * D_ + h * DK_;
    #pragma unroll
    for (int d = 0; d < DK_; d += 4) {
        *(float4*)(op + d) = make_float4(O[d] * inv, O[d + 1] * inv,
                                         O[d + 2] * inv, O[d + 3] * inv);
    }
}

/* =================================================================== */
extern "C" void kernel_launch(void* const* d_in, const int* in_sizes, int n_in,
                              void* d_out, int out_size)
{
    const float* x   = (const float*)d_in[0];
    const float* W_q = (const float*)d_in[1];
    const float* W_k = (const float*)d_in[2];
    const float* W_v = (const float*)d_in[3];
    const float* W_o = (const float*)d_in[4];
    float* out = (float*)d_out;

    float* qkv_ptr = nullptr;
    float* att_ptr = nullptr;
    cudaGetSymbolAddress((void**)&qkv_ptr, g_qkv);
    cudaGetSymbolAddress((void**)&att_ptr, g_att);

    cudaFuncSetAttribute(gemm_mma,
                         cudaFuncAttributeMaxDynamicSharedMemorySize, GEMM_SMEM);
    cudaFuncSetAttribute(attn_kernel,
                         cudaFuncAttributeMaxDynamicSharedMemorySize,
                         ATTN_SMEM_FLOATS * (int)sizeof(float));

    /* 1) QKV projection: g_qkv[8192,3072] = x @ [Wq|Wk|Wv]^T (tf32 mma) */
    {
        dim3 grid(N3_ / GBN, M_ / GBM);
        gemm_mma<<<grid, 256, GEMM_SMEM>>>(x, W_q, W_k, W_v, qkv_ptr, N3_);
    }

    /* 2) flash attention (fp32) -> g_att[8192,1024] */
    {
        dim3 grid(S_ / TQ_, B_ * H_);
        attn_kernel<<<grid, TQ_, ATTN_SMEM_FLOATS * sizeof(float)>>>(att_ptr);
    }

    /* 3) output projection: out = g_att @ W_out^T (tf32 mma) */
    {
        dim3 grid(D_ / GBN, M_ / GBM);
        gemm_mma<<<grid, 256, GEMM_SMEM>>>(att_ptr, W_o, W_o, W_o, out, D_);
    }
}

// round 4
// speedup vs baseline: 6.6203x; 2.9610x over previous
#include <cuda_runtime.h>
#include <math.h>
#include <stdint.h>

#define B_   4
#define S_   2048
#define D_   1024
#define H_   16
#define DK_  64
#define M_   (B_ * S_)        /* 8192 token rows */
#define N3_  (3 * D_)         /* 3072 */

/* Static scratch (no allocations allowed). */
__device__ float g_qkv[(size_t)M_ * N3_];
__device__ float g_att[(size_t)M_ * D_];

/* ======================= shared helpers ======================= */
__device__ __forceinline__ uint32_t f2tf32(float f) {
    uint32_t u;
    asm("cvt.rna.tf32.f32 %0, %1;" : "=r"(u) : "f"(f));
    return u;
}
__device__ __forceinline__ float ex2f(float x) {
    float y;
    asm("ex2.approx.ftz.f32 %0, %1;" : "=f"(y) : "f"(x));
    return y;
}
__device__ __forceinline__ void mma16n8k8(float* d, const uint32_t* a,
                                          uint32_t b0, uint32_t b1) {
    asm volatile(
        "mma.sync.aligned.m16n8k8.row.col.f32.tf32.tf32.f32 "
        "{%0,%1,%2,%3}, {%4,%5,%6,%7}, {%8,%9}, {%0,%1,%2,%3};"
        : "+f"(d[0]), "+f"(d[1]), "+f"(d[2]), "+f"(d[3])
        : "r"(a[0]), "r"(a[1]), "r"(a[2]), "r"(a[3]), "r"(b0), "r"(b1));
}

/* ===================================================================
 * tf32 mma.sync NT GEMM (unchanged from round 3 — 363us QKV, ~120us out)
 * =================================================================== */
#define GBM 128
#define GBN 128
#define GKB 32
#define NCHUNK (1024 / GKB)
#define ROWPAD 36
#define OPSTRIDE (128 * ROWPAD)
#define BUFSTRIDE (2 * OPSTRIDE)
#define GEMM_SMEM (2 * BUFSTRIDE * 4)

__global__ __launch_bounds__(256, 2)
void gemm_mma(const float* __restrict__ A,
              const float* __restrict__ B0,
              const float* __restrict__ B1,
              const float* __restrict__ B2,
              float* __restrict__ C, int Ntot)
{
    extern __shared__ uint32_t smu[];
    const int tid  = threadIdx.x;
    const int wid  = tid >> 5;
    const int lane = tid & 31;
    const int g    = lane >> 2;
    const int t    = lane & 3;
    const int wm   = wid & 3;
    const int wn   = wid >> 2;

    const int brow = blockIdx.y * GBM;
    const int bcol = blockIdx.x * GBN;
    const int mi   = bcol >> 10;
    const float* __restrict__ Bw = (mi == 0) ? B0 : ((mi == 1) ? B1 : B2);
    const int bcl  = bcol & 1023;
    const int K = 1024;

    const int frow = tid >> 3;
    const int fkq  = (tid & 7) * 4;

    float acc[2][8][4];
    #pragma unroll
    for (int mt = 0; mt < 2; mt++)
        #pragma unroll
        for (int nt = 0; nt < 8; nt++)
            #pragma unroll
            for (int j = 0; j < 4; j++)
                acc[mt][nt][j] = 0.0f;

    float4 pa[4], pb[4];

    #pragma unroll
    for (int i = 0; i < 4; i++) {
        const int r = frow + i * 32;
        pa[i] = *(const float4*)&A [(size_t)(brow + r) * K + fkq];
        pb[i] = *(const float4*)&Bw[(size_t)(bcl  + r) * K + fkq];
    }
    #pragma unroll
    for (int i = 0; i < 4; i++) {
        const int r = frow + i * 32;
        uint32_t* as = &smu[0 * OPSTRIDE + r * ROWPAD + fkq];
        uint32_t* bs = &smu[1 * OPSTRIDE + r * ROWPAD + fkq];
        as[0] = f2tf32(pa[i].x); as[1] = f2tf32(pa[i].y);
        as[2] = f2tf32(pa[i].z); as[3] = f2tf32(pa[i].w);
        bs[0] = f2tf32(pb[i].x); bs[1] = f2tf32(pb[i].y);
        bs[2] = f2tf32(pb[i].z); bs[3] = f2tf32(pb[i].w);
    }
    __syncthreads();

    for (int c = 0; c < NCHUNK; c++) {
        const int buf = c & 1;
        const uint32_t* As = &smu[buf * BUFSTRIDE];
        const uint32_t* Bs = &smu[buf * BUFSTRIDE + OPSTRIDE];

        if (c + 1 < NCHUNK) {
            const int k0 = (c + 1) * GKB;
            #pragma unroll
            for (int i = 0; i < 4; i++) {
                const int r = frow + i * 32;
                pa[i] = *(const float4*)&A [(size_t)(brow + r) * K + k0 + fkq];
                pb[i] = *(const float4*)&Bw[(size_t)(bcl  + r) * K + k0 + fkq];
            }
        }

        #pragma unroll
        for (int kk = 0; kk < GKB; kk += 8) {
            uint32_t afr[2][4];
            #pragma unroll
            for (int mt = 0; mt < 2; mt++) {
                const int r0 = wm * 32 + mt * 16 + g;
                afr[mt][0] = As[ r0      * ROWPAD + kk + t];
                afr[mt][1] = As[(r0 + 8) * ROWPAD + kk + t];
                afr[mt][2] = As[ r0      * ROWPAD + kk + t + 4];
                afr[mt][3] = As[(r0 + 8) * ROWPAD + kk + t + 4];
            }
            #pragma unroll
            for (int nt = 0; nt < 8; nt++) {
                const int n0 = wn * 64 + nt * 8 + g;
                const uint32_t b0 = Bs[n0 * ROWPAD + kk + t];
                const uint32_t b1 = Bs[n0 * ROWPAD + kk + t + 4];
                mma16n8k8(acc[0][nt], afr[0], b0, b1);
                mma16n8k8(acc[1][nt], afr[1], b0, b1);
            }
        }

        if (c + 1 < NCHUNK) {
            __syncthreads();
            const int nbuf = (c + 1) & 1;
            #pragma unroll
            for (int i = 0; i < 4; i++) {
                const int r = frow + i * 32;
                uint32_t* as = &smu[nbuf * BUFSTRIDE + r * ROWPAD + fkq];
                uint32_t* bs = &smu[nbuf * BUFSTRIDE + OPSTRIDE + r * ROWPAD + fkq];
                as[0] = f2tf32(pa[i].x); as[1] = f2tf32(pa[i].y);
                as[2] = f2tf32(pa[i].z); as[3] = f2tf32(pa[i].w);
                bs[0] = f2tf32(pb[i].x); bs[1] = f2tf32(pb[i].y);
                bs[2] = f2tf32(pb[i].z); bs[3] = f2tf32(pb[i].w);
            }
            __syncthreads();
        }
    }

    #pragma unroll
    for (int mt = 0; mt < 2; mt++) {
        const int row = brow + wm * 32 + mt * 16 + g;
        #pragma unroll
        for (int nt = 0; nt < 8; nt++) {
            const int col = bcol + wn * 64 + nt * 8 + 2 * t;
            float* cp0 = &C[(size_t)row * Ntot + col];
            float* cp1 = &C[(size_t)(row + 8) * Ntot + col];
            *(float2*)cp0 = make_float2(acc[mt][nt][0], acc[mt][nt][1]);
            *(float2*)cp1 = make_float2(acc[mt][nt][2], acc[mt][nt][3]);
        }
    }
}

/* ===================================================================
 * Flash attention on tf32 mma.sync.
 * CTA: 128 query rows (8 warps x 16 rows), key tile 64, d_k = 64.
 * smem rows padded to stride 68 words -> B-frag LDS banks = 4g+t.
 * Q fragments pinned in registers (scaled by 0.125*log2e, tf32).
 * Softmax in base-2 domain; P transposed acc->A-frag via quad shfl.
 * =================================================================== */
#define ASTRIDE 68
#define ATTN_SMEM ((128 + 64 + 64) * ASTRIDE * 4)   /* 69632 B */

__global__ __launch_bounds__(256, 1)
void attn_mma(float* __restrict__ out)
{
    extern __shared__ uint32_t smu[];
    uint32_t* Qs  = smu;                      /* [128][68] tf32 bits */
    uint32_t* Ksm = Qs  + 128 * ASTRIDE;      /* [64][68]  tf32 bits */
    uint32_t* Vsm = Ksm +  64 * ASTRIDE;      /* [64][68]  tf32 bits */

    const int tid  = threadIdx.x;
    const int wid  = tid >> 5;
    const int lane = tid & 31;
    const int g    = lane >> 2;
    const int t    = lane & 3;

    const int bh = blockIdx.y;
    const int b  = bh >> 4;
    const int h  = bh & 15;
    const size_t rowbase = (size_t)b * S_;
    const int qbase = blockIdx.x * 128;
    const float SCL = 0.125f * 1.4426950408889634f;   /* scale * log2(e) */

    const float* __restrict__ qkv = g_qkv;

    /* ---- stage Q tile (scaled + tf32) ---- */
    #pragma unroll
    for (int i = 0; i < 8; i++) {
        const int slot = tid + 256 * i;
        const int r  = slot >> 4;
        const int c4 = (slot & 15) * 4;
        float4 v = *(const float4*)&qkv[(rowbase + qbase + r) * N3_ + h * DK_ + c4];
        uint4 u;
        u.x = f2tf32(v.x * SCL); u.y = f2tf32(v.y * SCL);
        u.z = f2tf32(v.z * SCL); u.w = f2tf32(v.w * SCL);
        *(uint4*)&Qs[r * ASTRIDE + c4] = u;
    }
    __syncthreads();

    /* ---- Q fragments for this warp's 16 rows ---- */
    uint32_t qf[8][4];
    {
        const int r0 = wid * 16 + g;
        #pragma unroll
        for (int kc = 0; kc < 8; kc++) {
            qf[kc][0] = Qs[ r0      * ASTRIDE + kc * 8 + t];
            qf[kc][1] = Qs[(r0 + 8) * ASTRIDE + kc * 8 + t];
            qf[kc][2] = Qs[ r0      * ASTRIDE + kc * 8 + t + 4];
            qf[kc][3] = Qs[(r0 + 8) * ASTRIDE + kc * 8 + t + 4];
        }
    }

    float Oacc[8][4];
    #pragma unroll
    for (int n = 0; n < 8; n++)
        #pragma unroll
        for (int e = 0; e < 4; e++) Oacc[n][e] = 0.0f;
    float m0 = -1e30f, m1 = -1e30f, l0 = 0.0f, l1 = 0.0f;

    /* prefetch K/V tile 0 */
    float4 pk[4], pv[4];
    #pragma unroll
    for (int i = 0; i < 4; i++) {
        const int slot = tid + 256 * i;
        const int r  = slot >> 4;
        const int c4 = (slot & 15) * 4;
        pk[i] = *(const float4*)&qkv[(rowbase + r) * N3_ +     D_ + h * DK_ + c4];
        pv[i] = *(const float4*)&qkv[(rowbase + r) * N3_ + 2 * D_ + h * DK_ + c4];
    }

    const int srcA = (lane & 28) | (t >> 1);   /* quad base + t/2 */
    const int srcB = srcA + 2;

    for (int kt = 0; kt < 32; kt++) {
        __syncthreads();   /* previous tile's smem reads done */
        #pragma unroll
        for (int i = 0; i < 4; i++) {
            const int slot = tid + 256 * i;
            const int r  = slot >> 4;
            const int c4 = (slot & 15) * 4;
            uint4 uk, uv;
            uk.x = f2tf32(pk[i].x); uk.y = f2tf32(pk[i].y);
            uk.z = f2tf32(pk[i].z); uk.w = f2tf32(pk[i].w);
            uv.x = f2tf32(pv[i].x); uv.y = f2tf32(pv[i].y);
            uv.z = f2tf32(pv[i].z); uv.w = f2tf32(pv[i].w);
            *(uint4*)&Ksm[r * ASTRIDE + c4] = uk;
            *(uint4*)&Vsm[r * ASTRIDE + c4] = uv;
        }
        __syncthreads();

        /* prefetch next tile while computing this one */
        if (kt + 1 < 32) {
            const int kb = (kt + 1) * 64;
            #pragma unroll
            for (int i = 0; i < 4; i++) {
                const int slot = tid + 256 * i;
                const int r  = slot >> 4;
                const int c4 = (slot & 15) * 4;
                pk[i] = *(const float4*)&qkv[(rowbase + kb + r) * N3_ +     D_ + h * DK_ + c4];
                pv[i] = *(const float4*)&qkv[(rowbase + kb + r) * N3_ + 2 * D_ + h * DK_ + c4];
            }
        }

        /* ---- S = Q @ K^T (base-2 scaled) ---- */
        float sacc[8][4];
        #pragma unroll
        for (int n = 0; n < 8; n++)
            #pragma unroll
            for (int e = 0; e < 4; e++) sacc[n][e] = 0.0f;

        #pragma unroll
        for (int ks = 0; ks < 8; ks++) {
            #pragma unroll
            for (int nt = 0; nt < 8; nt++) {
                const uint32_t b0 = Ksm[(nt * 8 + g) * ASTRIDE + ks * 8 + t];
                const uint32_t b1 = Ksm[(nt * 8 + g) * ASTRIDE + ks * 8 + t + 4];
                mma16n8k8(sacc[nt], qf[ks], b0, b1);
            }
        }

        /* ---- online softmax (rows g and g+8) ---- */
        float rm0 = -1e30f, rm1 = -1e30f;
        #pragma unroll
        for (int nt = 0; nt < 8; nt++) {
            rm0 = fmaxf(rm0, fmaxf(sacc[nt][0], sacc[nt][1]));
            rm1 = fmaxf(rm1, fmaxf(sacc[nt][2], sacc[nt][3]));
        }
        rm0 = fmaxf(rm0, __shfl_xor_sync(0xffffffffu, rm0, 1));
        rm0 = fmaxf(rm0, __shfl_xor_sync(0xffffffffu, rm0, 2));
        rm1 = fmaxf(rm1, __shfl_xor_sync(0xffffffffu, rm1, 1));
        rm1 = fmaxf(rm1, __shfl_xor_sync(0xffffffffu, rm1, 2));

        const float mn0 = fmaxf(m0, rm0);
        const float mn1 = fmaxf(m1, rm1);
        const float corr0 = ex2f(m0 - mn0);
        const float corr1 = ex2f(m1 - mn1);

        float rs0 = 0.0f, rs1 = 0.0f;
        #pragma unroll
        for (int nt = 0; nt < 8; nt++) {
            sacc[nt][0] = ex2f(sacc[nt][0] - mn0);
            sacc[nt][1] = ex2f(sacc[nt][1] - mn0);
            sacc[nt][2] = ex2f(sacc[nt][2] - mn1);
            sacc[nt][3] = ex2f(sacc[nt][3] - mn1);
            rs0 += sacc[nt][0] + sacc[nt][1];
            rs1 += sacc[nt][2] + sacc[nt][3];
        }
        rs0 += __shfl_xor_sync(0xffffffffu, rs0, 1);
        rs0 += __shfl_xor_sync(0xffffffffu, rs0, 2);
        rs1 += __shfl_xor_sync(0xffffffffu, rs1, 1);
        rs1 += __shfl_xor_sync(0xffffffffu, rs1, 2);

        l0 = l0 * corr0 + rs0;
        l1 = l1 * corr1 + rs1;
        #pragma unroll
        for (int nt = 0; nt < 8; nt++) {
            Oacc[nt][0] *= corr0; Oacc[nt][1] *= corr0;
            Oacc[nt][2] *= corr1; Oacc[nt][3] *= corr1;
        }
        m0 = mn0; m1 = mn1;

        /* ---- O += P @ V  (P: acc layout -> A-frag via quad shfl) ---- */
        #pragma unroll
        for (int kc = 0; kc < 8; kc++) {
            const float x0  = __shfl_sync(0xffffffffu, sacc[kc][0], srcA);
            const float x1  = __shfl_sync(0xffffffffu, sacc[kc][1], srcA);
            const float y0  = __shfl_sync(0xffffffffu, sacc[kc][2], srcA);
            const float y1  = __shfl_sync(0xffffffffu, sacc[kc][3], srcA);
            const float x0b = __shfl_sync(0xffffffffu, sacc[kc][0], srcB);
            const float x1b = __shfl_sync(0xffffffffu, sacc[kc][1], srcB);
            const float y0b = __shfl_sync(0xffffffffu, sacc[kc][2], srcB);
            const float y1b = __shfl_sync(0xffffffffu, sacc[kc][3], srcB);
            uint32_t pf[4];
            pf[0] = f2tf32((t & 1) ? x1  : x0);
            pf[1] = f2tf32((t & 1) ? y1  : y0);
            pf[2] = f2tf32((t & 1) ? x1b : x0b);
            pf[3] = f2tf32((t & 1) ? y1b : y0b);
            #pragma unroll
            for (int nd = 0; nd < 8; nd++) {
                const uint32_t b0 = Vsm[(kc * 8 + t    ) * ASTRIDE + nd * 8 + g];
                const uint32_t b1 = Vsm[(kc * 8 + t + 4) * ASTRIDE + nd * 8 + g];
                mma16n8k8(Oacc[nd], pf, b0, b1);
            }
        }
    }

    /* ---- epilogue ---- */
    const float inv0 = 1.0f / l0;
    const float inv1 = 1.0f / l1;
    const size_t tok0 = rowbase + qbase + wid * 16 + g;
    const size_t tok1 = tok0 + 8;
    #pragma unroll
    for (int nd = 0; nd < 8; nd++) {
        const int col = h * DK_ + nd * 8 + 2 * t;
        *(float2*)&out[tok0 * D_ + col] =
            make_float2(Oacc[nd][0] * inv0, Oacc[nd][1] * inv0);
        *(float2*)&out[tok1 * D_ + col] =
            make_float2(Oacc[nd][2] * inv1, Oacc[nd][3] * inv1);
    }
}

/* =================================================================== */
extern "C" void kernel_launch(void* const* d_in, const int* in_sizes, int n_in,
                              void* d_out, int out_size)
{
    const float* x   = (const float*)d_in[0];
    const float* W_q = (const float*)d_in[1];
    const float* W_k = (const float*)d_in[2];
    const float* W_v = (const float*)d_in[3];
    const float* W_o = (const float*)d_in[4];
    float* out = (float*)d_out;

    float* qkv_ptr = nullptr;
    float* att_ptr = nullptr;
    cudaGetSymbolAddress((void**)&qkv_ptr, g_qkv);
    cudaGetSymbolAddress((void**)&att_ptr, g_att);

    cudaFuncSetAttribute(gemm_mma,
                         cudaFuncAttributeMaxDynamicSharedMemorySize, GEMM_SMEM);
    cudaFuncSetAttribute(attn_mma,
                         cudaFuncAttributeMaxDynamicSharedMemorySize, ATTN_SMEM);

    /* 1) QKV projection: g_qkv[8192,3072] = x @ [Wq|Wk|Wv]^T */
    {
        dim3 grid(N3_ / GBN, M_ / GBM);
        gemm_mma<<<grid, 256, GEMM_SMEM>>>(x, W_q, W_k, W_v, qkv_ptr, N3_);
    }

    /* 2) flash attention (tf32 mma) -> g_att[8192,1024] */
    {
        dim3 grid(S_ / 128, B_ * H_);
        attn_mma<<<grid, 256, ATTN_SMEM>>>(att_ptr);
    }

    /* 3) output projection: out = g_att @ W_out^T */
    {
        dim3 grid(D_ / GBN, M_ / GBM);
        gemm_mma<<<grid, 256, GEMM_SMEM>>>(att_ptr, W_o, W_o, W_o, out, D_);
    }
}

// round 6
// speedup vs baseline: 12.8787x; 1.9453x over previous
#include <cuda_runtime.h>
#include <cuda_fp16.h>
#include <math.h>
#include <stdint.h>

#define B_   4
#define S_   2048
#define D_   1024
#define H_   16
#define DK_  64
#define M_   (B_ * S_)
#define N3_  (3 * D_)

/* Static scratch in fp16 (same mantissa as tf32 for O(1) values). */
__device__ __half g_qkv[(size_t)M_ * N3_];   /* 50.3 MB */
__device__ __half g_att[(size_t)M_ * D_];    /* 16.8 MB */

/* ======================= helpers ======================= */
__device__ __forceinline__ uint32_t smem_u32(const void* p) {
    uint32_t a;
    asm("{ .reg .u64 t; cvta.to.shared.u64 t, %1; cvt.u32.u64 %0, t; }"
        : "=r"(a) : "l"(p));
    return a;
}
__device__ __forceinline__ float ex2f(float x) {
    float y;
    asm("ex2.approx.ftz.f32 %0, %1;" : "=f"(y) : "f"(x));
    return y;
}
__device__ __forceinline__ uint32_t h2u(__half2 v) {
    return *reinterpret_cast<uint32_t*>(&v);
}
__device__ __forceinline__ __half2 u2h(uint32_t u) {
    return *reinterpret_cast<__half2*>(&u);
}
__device__ __forceinline__ void ldmx4(uint32_t* r, uint32_t addr) {
    asm volatile("ldmatrix.sync.aligned.m8n8.x4.shared.b16 {%0,%1,%2,%3}, [%4];"
                 : "=r"(r[0]), "=r"(r[1]), "=r"(r[2]), "=r"(r[3]) : "r"(addr));
}
__device__ __forceinline__ void ldmx4t(uint32_t* r, uint32_t addr) {
    asm volatile("ldmatrix.sync.aligned.m8n8.x4.trans.shared.b16 {%0,%1,%2,%3}, [%4];"
                 : "=r"(r[0]), "=r"(r[1]), "=r"(r[2]), "=r"(r[3]) : "r"(addr));
}
__device__ __forceinline__ void mma_h(float* d, const uint32_t* a,
                                      uint32_t b0, uint32_t b1) {
    asm volatile(
        "mma.sync.aligned.m16n8k16.row.col.f32.f16.f16.f32 "
        "{%0,%1,%2,%3}, {%4,%5,%6,%7}, {%8,%9}, {%0,%1,%2,%3};"
        : "+f"(d[0]), "+f"(d[1]), "+f"(d[2]), "+f"(d[3])
        : "r"(a[0]), "r"(a[1]), "r"(a[2]), "r"(a[3]), "r"(b0), "r"(b1));
}

/* ===================================================================
 * fp16 mma NT GEMM: C[M, Ntot] = A[M,1024] @ Bcat[Ntot,1024]^T
 * 128x128 CTA tile, K-chunk 64 (128B rows), 8 warps (4M x 2N),
 * warp tile 32x64. Fragments via ldmatrix.x4 on XOR-swizzled smem.
 * A_HALF: A operand already fp16 (g_att); C_HALF: write fp16 (g_qkv).
 * smem: double buffer x (16KB A + 16KB B) = 64KB.
 * =================================================================== */
#define GEMM_SMEM 65536

template<bool A_HALF, bool C_HALF>
__global__ __launch_bounds__(256, 2)
void gemm_h(const void* __restrict__ Av,
            const float* __restrict__ B0, const float* __restrict__ B1,
            const float* __restrict__ B2,
            void* __restrict__ Cv, int Ntot)
{
    extern __shared__ char sm[];
    const uint32_t smb = smem_u32(sm);
    const int tid  = threadIdx.x;
    const int wid  = tid >> 5;
    const int lane = tid & 31;
    const int g    = lane >> 2, t = lane & 3;
    const int wm   = wid & 3,  wn = wid >> 2;
    const int mrow = lane & 7, mat = lane >> 3;
    const int matr = (mat & 1) * 8 + mrow;     /* row within 16-row group */
    const int cb   = mat >> 1;                 /* k-chunk offset 0/1 */

    const int brow = blockIdx.y * 128;
    const int bcol = blockIdx.x * 128;
    const int mi   = bcol >> 10;
    const float* __restrict__ Bw = (mi == 0) ? B0 : ((mi == 1) ? B1 : B2);
    const int bcl  = bcol & 1023;
    const int K = 1024;

    const __half* __restrict__ Ah = (const __half*)Av;
    const float*  __restrict__ Af = (const float*)Av;

    const int lr = tid >> 3;      /* 0..31 (+ i*32) */
    const int lc = tid & 7;       /* 16B chunk within 128B row */

    float acc[2][8][4];
    #pragma unroll
    for (int mt = 0; mt < 2; mt++)
        #pragma unroll
        for (int nt = 0; nt < 8; nt++)
            #pragma unroll
            for (int e = 0; e < 4; e++) acc[mt][nt][e] = 0.0f;

    uint4 pa[4], pb[4];

#define G_FETCH(k0) do {                                                       \
    _Pragma("unroll")                                                          \
    for (int i = 0; i < 4; i++) {                                              \
        const int r = lr + i * 32;                                             \
        if (A_HALF) {                                                          \
            pa[i] = *(const uint4*)&Ah[(size_t)(brow + r) * K + (k0) + lc * 8];\
        } else {                                                               \
            const float* ap = &Af[(size_t)(brow + r) * K + (k0) + lc * 8];     \
            float4 f0 = *(const float4*)ap, f1 = *(const float4*)(ap + 4);     \
            pa[i].x = h2u(__floats2half2_rn(f0.x, f0.y));                      \
            pa[i].y = h2u(__floats2half2_rn(f0.z, f0.w));                      \
            pa[i].z = h2u(__floats2half2_rn(f1.x, f1.y));                      \
            pa[i].w = h2u(__floats2half2_rn(f1.z, f1.w));                      \
        }                                                                      \
        const float* bp = &Bw[(size_t)(bcl + r) * K + (k0) + lc * 8];          \
        float4 g0 = *(const float4*)bp, g1 = *(const float4*)(bp + 4);         \
        pb[i].x = h2u(__floats2half2_rn(g0.x, g0.y));                          \
        pb[i].y = h2u(__floats2half2_rn(g0.z, g0.w));                          \
        pb[i].z = h2u(__floats2half2_rn(g1.x, g1.y));                          \
        pb[i].w = h2u(__floats2half2_rn(g1.z, g1.w));                          \
    }                                                                          \
} while (0)

#define G_STORE(buf) do {                                                      \
    char* bb = sm + (buf) * 32768;                                             \
    _Pragma("unroll")                                                          \
    for (int i = 0; i < 4; i++) {                                              \
        const int r = lr + i * 32;                                             \
        const int sw = r * 128 + ((lc ^ (r & 7)) << 4);                        \
        *(uint4*)(bb + sw)         = pa[i];                                    \
        *(uint4*)(bb + 16384 + sw) = pb[i];                                    \
    }                                                                          \
} while (0)

    G_FETCH(0);
    G_STORE(0);
    __syncthreads();

    for (int c = 0; c < 16; c++) {
        const int buf = c & 1;
        if (c + 1 < 16) G_FETCH((c + 1) * 64);

        const uint32_t sA = smb + buf * 32768u;
        const uint32_t sB = sA + 16384u;

        #pragma unroll
        for (int ks = 0; ks < 4; ks++) {
            const int xo = ((2 * ks + cb) ^ mrow) << 4;
            uint32_t af[2][4];
            #pragma unroll
            for (int mt = 0; mt < 2; mt++) {
                const int row = wm * 32 + mt * 16 + matr;
                ldmx4(af[mt], sA + row * 128 + xo);
            }
            #pragma unroll
            for (int j = 0; j < 4; j++) {
                const int nrow = wn * 64 + j * 16 + matr;
                uint32_t bf[4];
                ldmx4(bf, sB + nrow * 128 + xo);
                mma_h(acc[0][2 * j],     af[0], bf[0], bf[2]);
                mma_h(acc[1][2 * j],     af[1], bf[0], bf[2]);
                mma_h(acc[0][2 * j + 1], af[0], bf[1], bf[3]);
                mma_h(acc[1][2 * j + 1], af[1], bf[1], bf[3]);
            }
        }
        __syncthreads();
        if (c + 1 < 16) {
            G_STORE((c + 1) & 1);
            __syncthreads();
        }
    }

    #pragma unroll
    for (int mt = 0; mt < 2; mt++) {
        const int row = brow + wm * 32 + mt * 16 + g;
        #pragma unroll
        for (int nt = 0; nt < 8; nt++) {
            const int col = bcol + wn * 64 + nt * 8 + 2 * t;
            if (C_HALF) {
                __half* Ch = (__half*)Cv;
                *(__half2*)&Ch[(size_t)row * Ntot + col] =
                    __floats2half2_rn(acc[mt][nt][0], acc[mt][nt][1]);
                *(__half2*)&Ch[(size_t)(row + 8) * Ntot + col] =
                    __floats2half2_rn(acc[mt][nt][2], acc[mt][nt][3]);
            } else {
                float* Cf = (float*)Cv;
                *(float2*)&Cf[(size_t)row * Ntot + col] =
                    make_float2(acc[mt][nt][0], acc[mt][nt][1]);
                *(float2*)&Cf[(size_t)(row + 8) * Ntot + col] =
                    make_float2(acc[mt][nt][2], acc[mt][nt][3]);
            }
        }
    }
}
#undef G_FETCH
#undef G_STORE

/* ===================================================================
 * Flash attention, fp16 mma.m16n8k16.
 * CTA: 128 q-rows, 8 warps x 16 rows. 64-key tiles, d_k = 64.
 * Q/K/V staged in fp16 smem (128B rows, XOR swizzle); fragments via
 * ldmatrix; P accumulator packs directly into A-fragments (no shfl).
 * smem: Q 16KB + K 8KB + V 8KB = 32KB.
 * =================================================================== */
#define ATTN_SMEM 32768

__global__ __launch_bounds__(256, 2)
void attn_h()
{
    extern __shared__ char sm[];
    char* Qc = sm;
    char* Kc = sm + 16384;
    char* Vc = sm + 24576;
    const uint32_t smQ = smem_u32(Qc);
    const uint32_t smK = smQ + 16384;
    const uint32_t smV = smQ + 24576;

    const int tid  = threadIdx.x;
    const int wid  = tid >> 5;
    const int lane = tid & 31;
    const int g    = lane >> 2, t = lane & 3;
    const int mrow = lane & 7, mat = lane >> 3;
    const int matr = (mat & 1) * 8 + mrow;
    const int cb   = mat >> 1;
    const int lr   = tid >> 3;
    const int lc   = tid & 7;

    const int bh = blockIdx.y;
    const int b  = bh >> 4;
    const int h  = bh & 15;
    const size_t rowbase = (size_t)b * S_;
    const int qbase = blockIdx.x * 128;
    const float SCL = 0.125f * 1.4426950408889634f;

    const __half* __restrict__ qkv = g_qkv;
    __half* __restrict__ out = g_att;

    /* ---- stage Q (scaled) ---- */
    #pragma unroll
    for (int i = 0; i < 4; i++) {
        const int r = lr + i * 32;
        uint4 v = *(const uint4*)&qkv[(rowbase + qbase + r) * N3_ + h * DK_ + lc * 8];
        uint32_t w[4] = {v.x, v.y, v.z, v.w};
        #pragma unroll
        for (int e = 0; e < 4; e++) {
            float2 f = __half22float2(u2h(w[e]));
            w[e] = h2u(__floats2half2_rn(f.x * SCL, f.y * SCL));
        }
        uint4 o; o.x = w[0]; o.y = w[1]; o.z = w[2]; o.w = w[3];
        *(uint4*)(Qc + r * 128 + ((lc ^ (r & 7)) << 4)) = o;
    }
    __syncthreads();

    /* ---- Q fragments (warp's 16 rows, k = 64) ---- */
    uint32_t qf[4][4];
    {
        const int row = wid * 16 + matr;
        #pragma unroll
        for (int ks = 0; ks < 4; ks++)
            ldmx4(qf[ks], smQ + row * 128 + (((2 * ks + cb) ^ mrow) << 4));
    }

    float Oacc[8][4];
    #pragma unroll
    for (int nd = 0; nd < 8; nd++)
        #pragma unroll
        for (int e = 0; e < 4; e++) Oacc[nd][e] = 0.0f;
    float m0 = -1e30f, m1 = -1e30f, l0 = 0.0f, l1 = 0.0f;

    /* prefetch K/V tile 0 */
    uint4 pk[2], pv[2];
    #pragma unroll
    for (int i = 0; i < 2; i++) {
        const int r = lr + i * 32;
        pk[i] = *(const uint4*)&qkv[(rowbase + r) * N3_ +     D_ + h * DK_ + lc * 8];
        pv[i] = *(const uint4*)&qkv[(rowbase + r) * N3_ + 2 * D_ + h * DK_ + lc * 8];
    }

    for (int kt = 0; kt < 32; kt++) {
        __syncthreads();
        #pragma unroll
        for (int i = 0; i < 2; i++) {
            const int r = lr + i * 32;
            const int sw = r * 128 + ((lc ^ (r & 7)) << 4);
            *(uint4*)(Kc + sw) = pk[i];
            *(uint4*)(Vc + sw) = pv[i];
        }
        __syncthreads();

        if (kt + 1 < 32) {
            const int kb = (kt + 1) * 64;
            #pragma unroll
            for (int i = 0; i < 2; i++) {
                const int r = lr + i * 32;
                pk[i] = *(const uint4*)&qkv[(rowbase + kb + r) * N3_ +     D_ + h * DK_ + lc * 8];
                pv[i] = *(const uint4*)&qkv[(rowbase + kb + r) * N3_ + 2 * D_ + h * DK_ + lc * 8];
            }
        }

        /* ---- S = Q @ K^T ---- */
        float sacc[8][4];
        #pragma unroll
        for (int nt = 0; nt < 8; nt++)
            #pragma unroll
            for (int e = 0; e < 4; e++) sacc[nt][e] = 0.0f;

        #pragma unroll
        for (int ks = 0; ks < 4; ks++) {
            const int xo = ((2 * ks + cb) ^ mrow) << 4;
            #pragma unroll
            for (int j = 0; j < 4; j++) {
                uint32_t bf[4];
                ldmx4(bf, smK + (j * 16 + matr) * 128 + xo);
                mma_h(sacc[2 * j],     qf[ks], bf[0], bf[2]);
                mma_h(sacc[2 * j + 1], qf[ks], bf[1], bf[3]);
            }
        }

        /* ---- online softmax (rows g, g+8; base-2 domain) ---- */
        float rm0 = -1e30f, rm1 = -1e30f;
        #pragma unroll
        for (int nt = 0; nt < 8; nt++) {
            rm0 = fmaxf(rm0, fmaxf(sacc[nt][0], sacc[nt][1]));
            rm1 = fmaxf(rm1, fmaxf(sacc[nt][2], sacc[nt][3]));
        }
        rm0 = fmaxf(rm0, __shfl_xor_sync(0xffffffffu, rm0, 1));
        rm0 = fmaxf(rm0, __shfl_xor_sync(0xffffffffu, rm0, 2));
        rm1 = fmaxf(rm1, __shfl_xor_sync(0xffffffffu, rm1, 1));
        rm1 = fmaxf(rm1, __shfl_xor_sync(0xffffffffu, rm1, 2));

        const float mn0 = fmaxf(m0, rm0);
        const float mn1 = fmaxf(m1, rm1);
        const float corr0 = ex2f(m0 - mn0);
        const float corr1 = ex2f(m1 - mn1);

        float rs0 = 0.0f, rs1 = 0.0f;
        #pragma unroll
        for (int nt = 0; nt < 8; nt++) {
            sacc[nt][0] = ex2f(sacc[nt][0] - mn0);
            sacc[nt][1] = ex2f(sacc[nt][1] - mn0);
            sacc[nt][2] = ex2f(sacc[nt][2] - mn1);
            sacc[nt][3] = ex2f(sacc[nt][3] - mn1);
            rs0 += sacc[nt][0] + sacc[nt][1];
            rs1 += sacc[nt][2] + sacc[nt][3];
        }
        rs0 += __shfl_xor_sync(0xffffffffu, rs0, 1);
        rs0 += __shfl_xor_sync(0xffffffffu, rs0, 2);
        rs1 += __shfl_xor_sync(0xffffffffu, rs1, 1);
        rs1 += __shfl_xor_sync(0xffffffffu, rs1, 2);

        l0 = l0 * corr0 + rs0;
        l1 = l1 * corr1 + rs1;
        #pragma unroll
        for (int nd = 0; nd < 8; nd++) {
            Oacc[nd][0] *= corr0; Oacc[nd][1] *= corr0;
            Oacc[nd][2] *= corr1; Oacc[nd][3] *= corr1;
        }
        m0 = mn0; m1 = mn1;

        /* ---- O += P @ V  (P packs directly into A-frags) ---- */
        #pragma unroll
        for (int kc = 0; kc < 4; kc++) {
            uint32_t pf[4];
            pf[0] = h2u(__floats2half2_rn(sacc[2 * kc][0],     sacc[2 * kc][1]));
            pf[1] = h2u(__floats2half2_rn(sacc[2 * kc][2],     sacc[2 * kc][3]));
            pf[2] = h2u(__floats2half2_rn(sacc[2 * kc + 1][0], sacc[2 * kc + 1][1]));
            pf[3] = h2u(__floats2half2_rn(sacc[2 * kc + 1][2], sacc[2 * kc + 1][3]));
            const int tok = kc * 16 + matr;
            #pragma unroll
            for (int jd = 0; jd < 4; jd++) {
                uint32_t bf[4];
                ldmx4t(bf, smV + tok * 128 + (((2 * jd + cb) ^ mrow) << 4));
                mma_h(Oacc[2 * jd],     pf, bf[0], bf[1]);
                mma_h(Oacc[2 * jd + 1], pf, bf[2], bf[3]);
            }
        }
    }

    /* ---- epilogue (half output to g_att) ---- */
    const float inv0 = 1.0f / l0;
    const float inv1 = 1.0f / l1;
    const size_t tok0 = rowbase + qbase + wid * 16 + g;
    const size_t tok1 = tok0 + 8;
    #pragma unroll
    for (int nd = 0; nd < 8; nd++) {
        const int col = h * DK_ + nd * 8 + 2 * t;
        *(__half2*)&out[tok0 * D_ + col] =
            __floats2half2_rn(Oacc[nd][0] * inv0, Oacc[nd][1] * inv0);
        *(__half2*)&out[tok1 * D_ + col] =
            __floats2half2_rn(Oacc[nd][2] * inv1, Oacc[nd][3] * inv1);
    }
}

/* =================================================================== */
extern "C" void kernel_launch(void* const* d_in, const int* in_sizes, int n_in,
                              void* d_out, int out_size)
{
    const float* x   = (const float*)d_in[0];
    const float* W_q = (const float*)d_in[1];
    const float* W_k = (const float*)d_in[2];
    const float* W_v = (const float*)d_in[3];
    const float* W_o = (const float*)d_in[4];
    float* out = (float*)d_out;

    __half* qkv_ptr = nullptr;
    __half* att_ptr = nullptr;
    cudaGetSymbolAddress((void**)&qkv_ptr, g_qkv);
    cudaGetSymbolAddress((void**)&att_ptr, g_att);

    cudaFuncSetAttribute((const void*)gemm_h<false, true>,
                         cudaFuncAttributeMaxDynamicSharedMemorySize, GEMM_SMEM);
    cudaFuncSetAttribute((const void*)gemm_h<true, false>,
                         cudaFuncAttributeMaxDynamicSharedMemorySize, GEMM_SMEM);
    cudaFuncSetAttribute((const void*)attn_h,
                         cudaFuncAttributeMaxDynamicSharedMemorySize, ATTN_SMEM);

    /* 1) QKV projection: g_qkv[8192,3072](h) = x @ [Wq|Wk|Wv]^T */
    {
        dim3 grid(N3_ / 128, M_ / 128);
        gemm_h<false, true><<<grid, 256, GEMM_SMEM>>>(x, W_q, W_k, W_v,
                                                      qkv_ptr, N3_);
    }

    /* 2) flash attention (fp16 mma) -> g_att[8192,1024](h) */
    {
        dim3 grid(S_ / 128, B_ * H_);
        attn_h<<<grid, 256, ATTN_SMEM>>>();
    }

    /* 3) output projection: out(f32) = g_att @ W_out^T */
    {
        dim3 grid(D_ / 128, M_ / 128);
        gemm_h<true, false><<<grid, 256, GEMM_SMEM>>>(att_ptr, W_o, W_o, W_o,
                                                      out, D_);
    }
}

// round 8
// speedup vs baseline: 16.2376x; 1.2608x over previous
#include <cuda_runtime.h>
#include <cuda_fp16.h>
#include <math.h>
#include <stdint.h>

#define B_   4
#define S_   2048
#define D_   1024
#define H_   16
#define DK_  64
#define M_   (B_ * S_)
#define N3_  (3 * D_)

/* Static scratch (no allocations allowed). */
__device__ __half g_qkv[(size_t)M_ * N3_];    /* 50.3 MB */
__device__ __half g_att[(size_t)M_ * D_];     /* 16.8 MB */
__device__ __half g_xh [(size_t)M_ * D_];     /* 16.8 MB */
__device__ __half g_wh [(size_t)4 * D_ * D_]; /* 8.4 MB: Wq|Wk|Wv|Wo rows */

/* ======================= helpers ======================= */
__device__ __forceinline__ uint32_t smem_u32(const void* p) {
    uint32_t a;
    asm("{ .reg .u64 t; cvta.to.shared.u64 t, %1; cvt.u32.u64 %0, t; }"
        : "=r"(a) : "l"(p));
    return a;
}
__device__ __forceinline__ float ex2f(float x) {
    float y;
    asm("ex2.approx.ftz.f32 %0, %1;" : "=f"(y) : "f"(x));
    return y;
}
__device__ __forceinline__ uint32_t h2u(__half2 v) {
    return *reinterpret_cast<uint32_t*>(&v);
}
__device__ __forceinline__ __half2 u2h(uint32_t u) {
    return *reinterpret_cast<__half2*>(&u);
}
__device__ __forceinline__ void ldmx4(uint32_t* r, uint32_t addr) {
    asm volatile("ldmatrix.sync.aligned.m8n8.x4.shared.b16 {%0,%1,%2,%3}, [%4];"
                 : "=r"(r[0]), "=r"(r[1]), "=r"(r[2]), "=r"(r[3]) : "r"(addr));
}
__device__ __forceinline__ void ldmx4t(uint32_t* r, uint32_t addr) {
    asm volatile("ldmatrix.sync.aligned.m8n8.x4.trans.shared.b16 {%0,%1,%2,%3}, [%4];"
                 : "=r"(r[0]), "=r"(r[1]), "=r"(r[2]), "=r"(r[3]) : "r"(addr));
}
__device__ __forceinline__ void mma_h(float* d, const uint32_t* a,
                                      uint32_t b0, uint32_t b1) {
    asm volatile(
        "mma.sync.aligned.m16n8k16.row.col.f32.f16.f16.f32 "
        "{%0,%1,%2,%3}, {%4,%5,%6,%7}, {%8,%9}, {%0,%1,%2,%3};"
        : "+f"(d[0]), "+f"(d[1]), "+f"(d[2]), "+f"(d[3])
        : "r"(a[0]), "r"(a[1]), "r"(a[2]), "r"(a[3]), "r"(b0), "r"(b1));
}
__device__ __forceinline__ void cpasync16(uint32_t dst, const void* src) {
    asm volatile("cp.async.cg.shared.global [%0], [%1], 16;"
                 :: "r"(dst), "l"(__cvta_generic_to_global(src)));
}
#define CP_COMMIT() asm volatile("cp.async.commit_group;")
#define CP_WAIT2()  asm volatile("cp.async.wait_group 2;")

/* ======================= fp32 -> fp16 preprocess ======================= */
__global__ void cvt_x(const float* __restrict__ src, __half* __restrict__ dst)
{
    const int i = blockIdx.x * blockDim.x + threadIdx.x;  /* 4 floats each */
    float4 v = ((const float4*)src)[i];
    uint2 o;
    o.x = h2u(__floats2half2_rn(v.x, v.y));
    o.y = h2u(__floats2half2_rn(v.z, v.w));
    ((uint2*)dst)[i] = o;
}

__global__ void cvt_w(const float* __restrict__ w0, const float* __restrict__ w1,
                      const float* __restrict__ w2, const float* __restrict__ w3,
                      __half* __restrict__ dst)
{
    const int i = blockIdx.x * blockDim.x + threadIdx.x;  /* 4 floats each */
    const int m = i >> 18;                    /* 262144 float4 per matrix */
    const float* src = (m == 0) ? w0 : (m == 1) ? w1 : (m == 2) ? w2 : w3;
    float4 v = ((const float4*)src)[i & 262143];
    uint2 o;
    o.x = h2u(__floats2half2_rn(v.x, v.y));
    o.y = h2u(__floats2half2_rn(v.z, v.w));
    ((uint2*)dst)[i] = o;
}

/* ===================================================================
 * fp16 NT GEMM, cp.async 3-stage pipeline:
 *   C[M, Ntot] = A[M,1024](h) @ Bb[rows 0..Ntot-1,1024](h)^T
 * 128x128 CTA tile, K-chunk 64 (128B rows, XOR swizzle), 8 warps
 * (4M x 2N), warp tile 32x64. ldmatrix fragments, m16n8k16 mma.
 * smem: 3 stages x (16KB A + 16KB B) = 96KB; 2 CTAs/SM.
 * =================================================================== */
#define GEMM_SMEM (3 * 32768)

template<bool C_HALF>
__global__ __launch_bounds__(256, 2)
void gemm_h2(const __half* __restrict__ A, const __half* __restrict__ Bb,
             void* __restrict__ Cv, int Ntot)
{
    extern __shared__ char sm[];
    const uint32_t smb = smem_u32(sm);
    const int tid  = threadIdx.x;
    const int wid  = tid >> 5;
    const int lane = tid & 31;
    const int g    = lane >> 2, t = lane & 3;
    const int wm   = wid & 3,  wn = wid >> 2;
    const int mrow = lane & 7, mat = lane >> 3;
    const int matr = (mat & 1) * 8 + mrow;
    const int cb   = mat >> 1;
    const int lr   = tid >> 3;
    const int lc   = tid & 7;

    const int brow = blockIdx.y * 128;
    const int bcol = blockIdx.x * 128;   /* == global B row base (stacked W) */

    float acc[2][8][4];
    #pragma unroll
    for (int mt = 0; mt < 2; mt++)
        #pragma unroll
        for (int nt = 0; nt < 8; nt++)
            #pragma unroll
            for (int e = 0; e < 4; e++) acc[mt][nt][e] = 0.0f;

#define G_ISSUE(c) do {                                                        \
    if ((c) < 16) {                                                            \
        const uint32_t bb = smb + ((c) % 3) * 32768u;                          \
        const int k0 = (c) * 64;                                               \
        _Pragma("unroll")                                                      \
        for (int i = 0; i < 4; i++) {                                          \
            const int r = lr + i * 32;                                         \
            const uint32_t sw = r * 128 + ((lc ^ (r & 7)) << 4);               \
            cpasync16(bb + sw,                                                 \
                      &A [(size_t)(brow + r) * 1024 + k0 + lc * 8]);           \
            cpasync16(bb + 16384u + sw,                                        \
                      &Bb[(size_t)(bcol + r) * 1024 + k0 + lc * 8]);           \
        }                                                                      \
    }                                                                          \
    CP_COMMIT();                                                               \
} while (0)

    G_ISSUE(0);
    G_ISSUE(1);

    for (int c = 0; c < 16; c++) {
        G_ISSUE(c + 2);          /* into buf (c+2)%3 == chunk c-1's buffer */
        CP_WAIT2();              /* chunk c's data resident */
        __syncthreads();

        const uint32_t sA = smb + (c % 3) * 32768u;
        const uint32_t sB = sA + 16384u;

        #pragma unroll
        for (int ks = 0; ks < 4; ks++) {
            const int xo = ((2 * ks + cb) ^ mrow) << 4;
            uint32_t af[2][4];
            #pragma unroll
            for (int mt = 0; mt < 2; mt++)
                ldmx4(af[mt], sA + (wm * 32 + mt * 16 + matr) * 128 + xo);
            #pragma unroll
            for (int j = 0; j < 4; j++) {
                uint32_t bf[4];
                ldmx4(bf, sB + (wn * 64 + j * 16 + matr) * 128 + xo);
                mma_h(acc[0][2 * j],     af[0], bf[0], bf[2]);
                mma_h(acc[1][2 * j],     af[1], bf[0], bf[2]);
                mma_h(acc[0][2 * j + 1], af[0], bf[1], bf[3]);
                mma_h(acc[1][2 * j + 1], af[1], bf[1], bf[3]);
            }
        }
        __syncthreads();         /* reads done before next iter's issue */
    }
#undef G_ISSUE

    #pragma unroll
    for (int mt = 0; mt < 2; mt++) {
        const int row = brow + wm * 32 + mt * 16 + g;
        #pragma unroll
        for (int nt = 0; nt < 8; nt++) {
            const int col = bcol + wn * 64 + nt * 8 + 2 * t;
            if (C_HALF) {
                __half* Ch = (__half*)Cv;
                *(__half2*)&Ch[(size_t)row * Ntot + col] =
                    __floats2half2_rn(acc[mt][nt][0], acc[mt][nt][1]);
                *(__half2*)&Ch[(size_t)(row + 8) * Ntot + col] =
                    __floats2half2_rn(acc[mt][nt][2], acc[mt][nt][3]);
            } else {
                float* Cf = (float*)Cv;
                *(float2*)&Cf[(size_t)row * Ntot + col] =
                    make_float2(acc[mt][nt][0], acc[mt][nt][1]);
                *(float2*)&Cf[(size_t)(row + 8) * Ntot + col] =
                    make_float2(acc[mt][nt][2], acc[mt][nt][3]);
            }
        }
    }
}

/* ===================================================================
 * Flash attention, fp16 mma (unchanged from round 6 — ~210us).
 * =================================================================== */
#define ATTN_SMEM 32768

__global__ __launch_bounds__(256, 2)
void attn_h()
{
    extern __shared__ char sm[];
    char* Qc = sm;
    char* Kc = sm + 16384;
    char* Vc = sm + 24576;
    const uint32_t smQ = smem_u32(Qc);
    const uint32_t smK = smQ + 16384;
    const uint32_t smV = smQ + 24576;

    const int tid  = threadIdx.x;
    const int wid  = tid >> 5;
    const int lane = tid & 31;
    const int g    = lane >> 2, t = lane & 3;
    const int mrow = lane & 7, mat = lane >> 3;
    const int matr = (mat & 1) * 8 + mrow;
    const int cb   = mat >> 1;
    const int lr   = tid >> 3;
    const int lc   = tid & 7;

    const int bh = blockIdx.y;
    const int b  = bh >> 4;
    const int h  = bh & 15;
    const size_t rowbase = (size_t)b * S_;
    const int qbase = blockIdx.x * 128;
    const float SCL = 0.125f * 1.4426950408889634f;

    const __half* __restrict__ qkv = g_qkv;
    __half* __restrict__ out = g_att;

    #pragma unroll
    for (int i = 0; i < 4; i++) {
        const int r = lr + i * 32;
        uint4 v = *(const uint4*)&qkv[(rowbase + qbase + r) * N3_ + h * DK_ + lc * 8];
        uint32_t w[4] = {v.x, v.y, v.z, v.w};
        #pragma unroll
        for (int e = 0; e < 4; e++) {
            float2 f = __half22float2(u2h(w[e]));
            w[e] = h2u(__floats2half2_rn(f.x * SCL, f.y * SCL));
        }
        uint4 o; o.x = w[0]; o.y = w[1]; o.z = w[2]; o.w = w[3];
        *(uint4*)(Qc + r * 128 + ((lc ^ (r & 7)) << 4)) = o;
    }
    __syncthreads();

    uint32_t qf[4][4];
    {
        const int row = wid * 16 + matr;
        #pragma unroll
        for (int ks = 0; ks < 4; ks++)
            ldmx4(qf[ks], smQ + row * 128 + (((2 * ks + cb) ^ mrow) << 4));
    }

    float Oacc[8][4];
    #pragma unroll
    for (int nd = 0; nd < 8; nd++)
        #pragma unroll
        for (int e = 0; e < 4; e++) Oacc[nd][e] = 0.0f;
    float m0 = -1e30f, m1 = -1e30f, l0 = 0.0f, l1 = 0.0f;

    uint4 pk[2], pv[2];
    #pragma unroll
    for (int i = 0; i < 2; i++) {
        const int r = lr + i * 32;
        pk[i] = *(const uint4*)&qkv[(rowbase + r) * N3_ +     D_ + h * DK_ + lc * 8];
        pv[i] = *(const uint4*)&qkv[(rowbase + r) * N3_ + 2 * D_ + h * DK_ + lc * 8];
    }

    for (int kt = 0; kt < 32; kt++) {
        __syncthreads();
        #pragma unroll
        for (int i = 0; i < 2; i++) {
            const int r = lr + i * 32;
            const int sw = r * 128 + ((lc ^ (r & 7)) << 4);
            *(uint4*)(Kc + sw) = pk[i];
            *(uint4*)(Vc + sw) = pv[i];
        }
        __syncthreads();

        if (kt + 1 < 32) {
            const int kb = (kt + 1) * 64;
            #pragma unroll
            for (int i = 0; i < 2; i++) {
                const int r = lr + i * 32;
                pk[i] = *(const uint4*)&qkv[(rowbase + kb + r) * N3_ +     D_ + h * DK_ + lc * 8];
                pv[i] = *(const uint4*)&qkv[(rowbase + kb + r) * N3_ + 2 * D_ + h * DK_ + lc * 8];
            }
        }

        float sacc[8][4];
        #pragma unroll
        for (int nt = 0; nt < 8; nt++)
            #pragma unroll
            for (int e = 0; e < 4; e++) sacc[nt][e] = 0.0f;

        #pragma unroll
        for (int ks = 0; ks < 4; ks++) {
            const int xo = ((2 * ks + cb) ^ mrow) << 4;
            #pragma unroll
            for (int j = 0; j < 4; j++) {
                uint32_t bf[4];
                ldmx4(bf, smK + (j * 16 + matr) * 128 + xo);
                mma_h(sacc[2 * j],     qf[ks], bf[0], bf[2]);
                mma_h(sacc[2 * j + 1], qf[ks], bf[1], bf[3]);
            }
        }

        float rm0 = -1e30f, rm1 = -1e30f;
        #pragma unroll
        for (int nt = 0; nt < 8; nt++) {
            rm0 = fmaxf(rm0, fmaxf(sacc[nt][0], sacc[nt][1]));
            rm1 = fmaxf(rm1, fmaxf(sacc[nt][2], sacc[nt][3]));
        }
        rm0 = fmaxf(rm0, __shfl_xor_sync(0xffffffffu, rm0, 1));
        rm0 = fmaxf(rm0, __shfl_xor_sync(0xffffffffu, rm0, 2));
        rm1 = fmaxf(rm1, __shfl_xor_sync(0xffffffffu, rm1, 1));
        rm1 = fmaxf(rm1, __shfl_xor_sync(0xffffffffu, rm1, 2));

        const float mn0 = fmaxf(m0, rm0);
        const float mn1 = fmaxf(m1, rm1);
        const float corr0 = ex2f(m0 - mn0);
        const float corr1 = ex2f(m1 - mn1);

        float rs0 = 0.0f, rs1 = 0.0f;
        #pragma unroll
        for (int nt = 0; nt < 8; nt++) {
            sacc[nt][0] = ex2f(sacc[nt][0] - mn0);
            sacc[nt][1] = ex2f(sacc[nt][1] - mn0);
            sacc[nt][2] = ex2f(sacc[nt][2] - mn1);
            sacc[nt][3] = ex2f(sacc[nt][3] - mn1);
            rs0 += sacc[nt][0] + sacc[nt][1];
            rs1 += sacc[nt][2] + sacc[nt][3];
        }
        rs0 += __shfl_xor_sync(0xffffffffu, rs0, 1);
        rs0 += __shfl_xor_sync(0xffffffffu, rs0, 2);
        rs1 += __shfl_xor_sync(0xffffffffu, rs1, 1);
        rs1 += __shfl_xor_sync(0xffffffffu, rs1, 2);

        l0 = l0 * corr0 + rs0;
        l1 = l1 * corr1 + rs1;
        #pragma unroll
        for (int nd = 0; nd < 8; nd++) {
            Oacc[nd][0] *= corr0; Oacc[nd][1] *= corr0;
            Oacc[nd][2] *= corr1; Oacc[nd][3] *= corr1;
        }
        m0 = mn0; m1 = mn1;

        #pragma unroll
        for (int kc = 0; kc < 4; kc++) {
            uint32_t pf[4];
            pf[0] = h2u(__floats2half2_rn(sacc[2 * kc][0],     sacc[2 * kc][1]));
            pf[1] = h2u(__floats2half2_rn(sacc[2 * kc][2],     sacc[2 * kc][3]));
            pf[2] = h2u(__floats2half2_rn(sacc[2 * kc + 1][0], sacc[2 * kc + 1][1]));
            pf[3] = h2u(__floats2half2_rn(sacc[2 * kc + 1][2], sacc[2 * kc + 1][3]));
            const int tok = kc * 16 + matr;
            #pragma unroll
            for (int jd = 0; jd < 4; jd++) {
                uint32_t bf[4];
                ldmx4t(bf, smV + tok * 128 + (((2 * jd + cb) ^ mrow) << 4));
                mma_h(Oacc[2 * jd],     pf, bf[0], bf[1]);
                mma_h(Oacc[2 * jd + 1], pf, bf[2], bf[3]);
            }
        }
    }

    const float inv0 = 1.0f / l0;
    const float inv1 = 1.0f / l1;
    const size_t tok0 = rowbase + qbase + wid * 16 + g;
    const size_t tok1 = tok0 + 8;
    #pragma unroll
    for (int nd = 0; nd < 8; nd++) {
        const int col = h * DK_ + nd * 8 + 2 * t;
        *(__half2*)&out[tok0 * D_ + col] =
            __floats2half2_rn(Oacc[nd][0] * inv0, Oacc[nd][1] * inv0);
        *(__half2*)&out[tok1 * D_ + col] =
            __floats2half2_rn(Oacc[nd][2] * inv1, Oacc[nd][3] * inv1);
    }
}

/* =================================================================== */
extern "C" void kernel_launch(void* const* d_in, const int* in_sizes, int n_in,
                              void* d_out, int out_size)
{
    const float* x   = (const float*)d_in[0];
    const float* W_q = (const float*)d_in[1];
    const float* W_k = (const float*)d_in[2];
    const float* W_v = (const float*)d_in[3];
    const float* W_o = (const float*)d_in[4];
    float* out = (float*)d_out;

    __half *qkv_ptr = nullptr, *att_ptr = nullptr, *xh_ptr = nullptr, *wh_ptr = nullptr;
    cudaGetSymbolAddress((void**)&qkv_ptr, g_qkv);
    cudaGetSymbolAddress((void**)&att_ptr, g_att);
    cudaGetSymbolAddress((void**)&xh_ptr,  g_xh);
    cudaGetSymbolAddress((void**)&wh_ptr,  g_wh);

    cudaFuncSetAttribute((const void*)gemm_h2<true>,
                         cudaFuncAttributeMaxDynamicSharedMemorySize, GEMM_SMEM);
    cudaFuncSetAttribute((const void*)gemm_h2<false>,
                         cudaFuncAttributeMaxDynamicSharedMemorySize, GEMM_SMEM);
    cudaFuncSetAttribute((const void*)attn_h,
                         cudaFuncAttributeMaxDynamicSharedMemorySize, ATTN_SMEM);

    /* 0) fp32 -> fp16 operand staging */
    cvt_x<<<(M_ * D_ / 4) / 256, 256>>>(x, xh_ptr);
    cvt_w<<<(4 * D_ * D_ / 4) / 256, 256>>>(W_q, W_k, W_v, W_o, wh_ptr);

    /* 1) QKV projection: g_qkv[8192,3072](h) = xh @ [Wq|Wk|Wv]^T */
    {
        dim3 grid(N3_ / 128, M_ / 128);
        gemm_h2<true><<<grid, 256, GEMM_SMEM>>>(xh_ptr, wh_ptr, qkv_ptr, N3_);
    }

    /* 2) flash attention (fp16 mma) -> g_att[8192,1024](h) */
    {
        dim3 grid(S_ / 128, B_ * H_);
        attn_h<<<grid, 256, ATTN_SMEM>>>();
    }

    /* 3) output projection: out(f32) = g_att @ Wo^T */
    {
        dim3 grid(D_ / 128, M_ / 128);
        gemm_h2<false><<<grid, 256, GEMM_SMEM>>>(att_ptr,
                                                 wh_ptr + (size_t)3 * D_ * D_,
                                                 out, D_);
    }
}

// round 9
// speedup vs baseline: 16.6513x; 1.0255x over previous
#include <cuda_runtime.h>
#include <cuda_fp16.h>
#include <math.h>
#include <stdint.h>

#define B_   4
#define S_   2048
#define D_   1024
#define H_   16
#define DK_  64
#define M_   (B_ * S_)
#define N3_  (3 * D_)

/* Static scratch (no allocations allowed). */
__device__ __half g_qkv[(size_t)M_ * N3_];    /* 50.3 MB */
__device__ __half g_att[(size_t)M_ * D_];     /* 16.8 MB */
__device__ __half g_xh [(size_t)M_ * D_];     /* 16.8 MB */
__device__ __half g_wh [(size_t)4 * D_ * D_]; /* 8.4 MB: Wq|Wk|Wv|Wo rows */

/* ======================= helpers ======================= */
__device__ __forceinline__ uint32_t smem_u32(const void* p) {
    uint32_t a;
    asm("{ .reg .u64 t; cvta.to.shared.u64 t, %1; cvt.u32.u64 %0, t; }"
        : "=r"(a) : "l"(p));
    return a;
}
__device__ __forceinline__ float ex2f(float x) {
    float y;
    asm("ex2.approx.ftz.f32 %0, %1;" : "=f"(y) : "f"(x));
    return y;
}
__device__ __forceinline__ uint32_t h2u(__half2 v) {
    return *reinterpret_cast<uint32_t*>(&v);
}
__device__ __forceinline__ __half2 u2h(uint32_t u) {
    return *reinterpret_cast<__half2*>(&u);
}
__device__ __forceinline__ void ldmx4(uint32_t* r, uint32_t addr) {
    asm volatile("ldmatrix.sync.aligned.m8n8.x4.shared.b16 {%0,%1,%2,%3}, [%4];"
                 : "=r"(r[0]), "=r"(r[1]), "=r"(r[2]), "=r"(r[3]) : "r"(addr));
}
__device__ __forceinline__ void ldmx4t(uint32_t* r, uint32_t addr) {
    asm volatile("ldmatrix.sync.aligned.m8n8.x4.trans.shared.b16 {%0,%1,%2,%3}, [%4];"
                 : "=r"(r[0]), "=r"(r[1]), "=r"(r[2]), "=r"(r[3]) : "r"(addr));
}
__device__ __forceinline__ void mma_h(float* d, const uint32_t* a,
                                      uint32_t b0, uint32_t b1) {
    asm volatile(
        "mma.sync.aligned.m16n8k16.row.col.f32.f16.f16.f32 "
        "{%0,%1,%2,%3}, {%4,%5,%6,%7}, {%8,%9}, {%0,%1,%2,%3};"
        : "+f"(d[0]), "+f"(d[1]), "+f"(d[2]), "+f"(d[3])
        : "r"(a[0]), "r"(a[1]), "r"(a[2]), "r"(a[3]), "r"(b0), "r"(b1));
}
__device__ __forceinline__ void cpasync16(uint32_t dst, const void* src) {
    asm volatile("cp.async.cg.shared.global [%0], [%1], 16;"
                 :: "r"(dst), "l"(__cvta_generic_to_global(src)));
}
#define CP_COMMIT() asm volatile("cp.async.commit_group;")
#define CP_WAIT2()  asm volatile("cp.async.wait_group 2;")

/* ======================= fp32 -> fp16 preprocess ======================= */
__global__ void cvt_x(const float* __restrict__ src, __half* __restrict__ dst)
{
    const int i = blockIdx.x * blockDim.x + threadIdx.x;
    float4 v = ((const float4*)src)[i];
    uint2 o;
    o.x = h2u(__floats2half2_rn(v.x, v.y));
    o.y = h2u(__floats2half2_rn(v.z, v.w));
    ((uint2*)dst)[i] = o;
}

__global__ void cvt_w(const float* __restrict__ w0, const float* __restrict__ w1,
                      const float* __restrict__ w2, const float* __restrict__ w3,
                      __half* __restrict__ dst)
{
    const int i = blockIdx.x * blockDim.x + threadIdx.x;
    const int m = i >> 18;
    const float* src = (m == 0) ? w0 : (m == 1) ? w1 : (m == 2) ? w2 : w3;
    float4 v = ((const float4*)src)[i & 262143];
    uint2 o;
    o.x = h2u(__floats2half2_rn(v.x, v.y));
    o.y = h2u(__floats2half2_rn(v.z, v.w));
    ((uint2*)dst)[i] = o;
}

/* ===================================================================
 * fp16 NT GEMM, cp.async 3-stage pipeline (unchanged from round 7).
 * =================================================================== */
#define GEMM_SMEM (3 * 32768)

template<bool C_HALF>
__global__ __launch_bounds__(256, 2)
void gemm_h2(const __half* __restrict__ A, const __half* __restrict__ Bb,
             void* __restrict__ Cv, int Ntot)
{
    extern __shared__ char sm[];
    const uint32_t smb = smem_u32(sm);
    const int tid  = threadIdx.x;
    const int wid  = tid >> 5;
    const int lane = tid & 31;
    const int g    = lane >> 2, t = lane & 3;
    const int wm   = wid & 3,  wn = wid >> 2;
    const int mrow = lane & 7, mat = lane >> 3;
    const int matr = (mat & 1) * 8 + mrow;
    const int cb   = mat >> 1;
    const int lr   = tid >> 3;
    const int lc   = tid & 7;

    const int brow = blockIdx.y * 128;
    const int bcol = blockIdx.x * 128;

    float acc[2][8][4];
    #pragma unroll
    for (int mt = 0; mt < 2; mt++)
        #pragma unroll
        for (int nt = 0; nt < 8; nt++)
            #pragma unroll
            for (int e = 0; e < 4; e++) acc[mt][nt][e] = 0.0f;

#define G_ISSUE(c) do {                                                        \
    if ((c) < 16) {                                                            \
        const uint32_t bb = smb + ((c) % 3) * 32768u;                          \
        const int k0 = (c) * 64;                                               \
        _Pragma("unroll")                                                      \
        for (int i = 0; i < 4; i++) {                                          \
            const int r = lr + i * 32;                                         \
            const uint32_t sw = r * 128 + ((lc ^ (r & 7)) << 4);               \
            cpasync16(bb + sw,                                                 \
                      &A [(size_t)(brow + r) * 1024 + k0 + lc * 8]);           \
            cpasync16(bb + 16384u + sw,                                        \
                      &Bb[(size_t)(bcol + r) * 1024 + k0 + lc * 8]);           \
        }                                                                      \
    }                                                                          \
    CP_COMMIT();                                                               \
} while (0)

    G_ISSUE(0);
    G_ISSUE(1);

    for (int c = 0; c < 16; c++) {
        G_ISSUE(c + 2);
        CP_WAIT2();
        __syncthreads();

        const uint32_t sA = smb + (c % 3) * 32768u;
        const uint32_t sB = sA + 16384u;

        #pragma unroll
        for (int ks = 0; ks < 4; ks++) {
            const int xo = ((2 * ks + cb) ^ mrow) << 4;
            uint32_t af[2][4];
            #pragma unroll
            for (int mt = 0; mt < 2; mt++)
                ldmx4(af[mt], sA + (wm * 32 + mt * 16 + matr) * 128 + xo);
            #pragma unroll
            for (int j = 0; j < 4; j++) {
                uint32_t bf[4];
                ldmx4(bf, sB + (wn * 64 + j * 16 + matr) * 128 + xo);
                mma_h(acc[0][2 * j],     af[0], bf[0], bf[2]);
                mma_h(acc[1][2 * j],     af[1], bf[0], bf[2]);
                mma_h(acc[0][2 * j + 1], af[0], bf[1], bf[3]);
                mma_h(acc[1][2 * j + 1], af[1], bf[1], bf[3]);
            }
        }
        __syncthreads();
    }
#undef G_ISSUE

    #pragma unroll
    for (int mt = 0; mt < 2; mt++) {
        const int row = brow + wm * 32 + mt * 16 + g;
        #pragma unroll
        for (int nt = 0; nt < 8; nt++) {
            const int col = bcol + wn * 64 + nt * 8 + 2 * t;
            if (C_HALF) {
                __half* Ch = (__half*)Cv;
                *(__half2*)&Ch[(size_t)row * Ntot + col] =
                    __floats2half2_rn(acc[mt][nt][0], acc[mt][nt][1]);
                *(__half2*)&Ch[(size_t)(row + 8) * Ntot + col] =
                    __floats2half2_rn(acc[mt][nt][2], acc[mt][nt][3]);
            } else {
                float* Cf = (float*)Cv;
                *(float2*)&Cf[(size_t)row * Ntot + col] =
                    make_float2(acc[mt][nt][0], acc[mt][nt][1]);
                *(float2*)&Cf[(size_t)(row + 8) * Ntot + col] =
                    make_float2(acc[mt][nt][2], acc[mt][nt][3]);
            }
        }
    }
}

/* ===================================================================
 * Flash attention, fp16 mma + cp.async 3-stage K/V pipeline.
 * CTA: 128 q-rows, 8 warps x 16 rows; 64-key tiles; d_k = 64.
 * smem: Q 16KB + 3 stages x (K 8KB + V 8KB) = 64KB; 2 CTAs/SM.
 * Q loaded via cp.async; softmax scale applied to Q fragments in regs.
 * =================================================================== */
#define ATTN_SMEM 65536

__global__ __launch_bounds__(256, 2)
void attn_h()
{
    extern __shared__ char sm[];
    const uint32_t smQ  = smem_u32(sm);
    const uint32_t smKV = smQ + 16384;    /* stage s at smKV + s*16384 */

    const int tid  = threadIdx.x;
    const int wid  = tid >> 5;
    const int lane = tid & 31;
    const int g    = lane >> 2, t = lane & 3;
    const int mrow = lane & 7, mat = lane >> 3;
    const int matr = (mat & 1) * 8 + mrow;
    const int cb   = mat >> 1;
    const int lr   = tid >> 3;            /* 0..31 */
    const int lc   = tid & 7;

    const int bh = blockIdx.y;
    const int b  = bh >> 4;
    const int h  = bh & 15;
    const size_t rowbase = (size_t)b * S_;
    const int qbase = blockIdx.x * 128;

    const __half* __restrict__ qkv = g_qkv;
    __half* __restrict__ out = g_att;

    /* ---- issue Q (group folded into stage-0 commit) ---- */
    #pragma unroll
    for (int i = 0; i < 4; i++) {
        const int r = lr + i * 32;
        cpasync16(smQ + r * 128 + ((lc ^ (r & 7)) << 4),
                  &qkv[(rowbase + qbase + r) * N3_ + h * DK_ + lc * 8]);
    }

#define KV_ISSUE(kt) do {                                                      \
    if ((kt) < 32) {                                                           \
        const uint32_t bb = smKV + ((kt) % 3) * 16384u;                        \
        const int kb = (kt) * 64;                                              \
        _Pragma("unroll")                                                      \
        for (int i = 0; i < 2; i++) {                                          \
            const int r = lr + i * 32;                                         \
            const uint32_t sw = r * 128 + ((lc ^ (r & 7)) << 4);               \
            cpasync16(bb + sw,                                                 \
                      &qkv[(rowbase + kb + r) * N3_ +     D_ + h * DK_ + lc * 8]); \
            cpasync16(bb + 8192u + sw,                                         \
                      &qkv[(rowbase + kb + r) * N3_ + 2 * D_ + h * DK_ + lc * 8]); \
        }                                                                      \
    }                                                                          \
    CP_COMMIT();                                                               \
} while (0)

    KV_ISSUE(0);     /* group 0: Q + KV tile 0 */
    KV_ISSUE(1);     /* group 1: KV tile 1 */

    uint32_t qf[4][4];
    float Oacc[8][4];
    #pragma unroll
    for (int nd = 0; nd < 8; nd++)
        #pragma unroll
        for (int e = 0; e < 4; e++) Oacc[nd][e] = 0.0f;
    float m0 = -1e30f, m1 = -1e30f, l0 = 0.0f, l1 = 0.0f;

    for (int kt = 0; kt < 32; kt++) {
        KV_ISSUE(kt + 2);
        CP_WAIT2();           /* group kt complete (incl. Q on kt=0) */
        __syncthreads();

        if (kt == 0) {
            /* one-time Q fragment load + in-register softmax scale */
            const __half2 scl2 = __float2half2_rn(0.125f * 1.4426950408889634f);
            const int row = wid * 16 + matr;
            #pragma unroll
            for (int ks = 0; ks < 4; ks++) {
                ldmx4(qf[ks], smQ + row * 128 + (((2 * ks + cb) ^ mrow) << 4));
                #pragma unroll
                for (int e = 0; e < 4; e++)
                    qf[ks][e] = h2u(__hmul2(u2h(qf[ks][e]), scl2));
            }
        }

        const uint32_t sK = smKV + (kt % 3) * 16384u;
        const uint32_t sV = sK + 8192u;

        /* ---- S = Q @ K^T ---- */
        float sacc[8][4];
        #pragma unroll
        for (int nt = 0; nt < 8; nt++)
            #pragma unroll
            for (int e = 0; e < 4; e++) sacc[nt][e] = 0.0f;

        #pragma unroll
        for (int ks = 0; ks < 4; ks++) {
            const int xo = ((2 * ks + cb) ^ mrow) << 4;
            #pragma unroll
            for (int j = 0; j < 4; j++) {
                uint32_t bf[4];
                ldmx4(bf, sK + (j * 16 + matr) * 128 + xo);
                mma_h(sacc[2 * j],     qf[ks], bf[0], bf[2]);
                mma_h(sacc[2 * j + 1], qf[ks], bf[1], bf[3]);
            }
        }

        /* ---- online softmax (rows g, g+8; base-2 domain) ---- */
        float rm0 = -1e30f, rm1 = -1e30f;
        #pragma unroll
        for (int nt = 0; nt < 8; nt++) {
            rm0 = fmaxf(rm0, fmaxf(sacc[nt][0], sacc[nt][1]));
            rm1 = fmaxf(rm1, fmaxf(sacc[nt][2], sacc[nt][3]));
        }
        rm0 = fmaxf(rm0, __shfl_xor_sync(0xffffffffu, rm0, 1));
        rm0 = fmaxf(rm0, __shfl_xor_sync(0xffffffffu, rm0, 2));
        rm1 = fmaxf(rm1, __shfl_xor_sync(0xffffffffu, rm1, 1));
        rm1 = fmaxf(rm1, __shfl_xor_sync(0xffffffffu, rm1, 2));

        const float mn0 = fmaxf(m0, rm0);
        const float mn1 = fmaxf(m1, rm1);
        const float corr0 = ex2f(m0 - mn0);
        const float corr1 = ex2f(m1 - mn1);

        float rs0 = 0.0f, rs1 = 0.0f;
        #pragma unroll
        for (int nt = 0; nt < 8; nt++) {
            sacc[nt][0] = ex2f(sacc[nt][0] - mn0);
            sacc[nt][1] = ex2f(sacc[nt][1] - mn0);
            sacc[nt][2] = ex2f(sacc[nt][2] - mn1);
            sacc[nt][3] = ex2f(sacc[nt][3] - mn1);
            rs0 += sacc[nt][0] + sacc[nt][1];
            rs1 += sacc[nt][2] + sacc[nt][3];
        }
        rs0 += __shfl_xor_sync(0xffffffffu, rs0, 1);
        rs0 += __shfl_xor_sync(0xffffffffu, rs0, 2);
        rs1 += __shfl_xor_sync(0xffffffffu, rs1, 1);
        rs1 += __shfl_xor_sync(0xffffffffu, rs1, 2);

        l0 = l0 * corr0 + rs0;
        l1 = l1 * corr1 + rs1;
        #pragma unroll
        for (int nd = 0; nd < 8; nd++) {
            Oacc[nd][0] *= corr0; Oacc[nd][1] *= corr0;
            Oacc[nd][2] *= corr1; Oacc[nd][3] *= corr1;
        }
        m0 = mn0; m1 = mn1;

        /* ---- O += P @ V ---- */
        #pragma unroll
        for (int kc = 0; kc < 4; kc++) {
            uint32_t pf[4];
            pf[0] = h2u(__floats2half2_rn(sacc[2 * kc][0],     sacc[2 * kc][1]));
            pf[1] = h2u(__floats2half2_rn(sacc[2 * kc][2],     sacc[2 * kc][3]));
            pf[2] = h2u(__floats2half2_rn(sacc[2 * kc + 1][0], sacc[2 * kc + 1][1]));
            pf[3] = h2u(__floats2half2_rn(sacc[2 * kc + 1][2], sacc[2 * kc + 1][3]));
            const int tok = kc * 16 + matr;
            #pragma unroll
            for (int jd = 0; jd < 4; jd++) {
                uint32_t bf[4];
                ldmx4t(bf, sV + tok * 128 + (((2 * jd + cb) ^ mrow) << 4));
                mma_h(Oacc[2 * jd],     pf, bf[0], bf[1]);
                mma_h(Oacc[2 * jd + 1], pf, bf[2], bf[3]);
            }
        }
        __syncthreads();   /* stage reads done before its re-issue */
    }
#undef KV_ISSUE

    /* ---- epilogue ---- */
    const float inv0 = 1.0f / l0;
    const float inv1 = 1.0f / l1;
    const size_t tok0 = rowbase + qbase + wid * 16 + g;
    const size_t tok1 = tok0 + 8;
    #pragma unroll
    for (int nd = 0; nd < 8; nd++) {
        const int col = h * DK_ + nd * 8 + 2 * t;
        *(__half2*)&out[tok0 * D_ + col] =
            __floats2half2_rn(Oacc[nd][0] * inv0, Oacc[nd][1] * inv0);
        *(__half2*)&out[tok1 * D_ + col] =
            __floats2half2_rn(Oacc[nd][2] * inv1, Oacc[nd][3] * inv1);
    }
}

/* =================================================================== */
extern "C" void kernel_launch(void* const* d_in, const int* in_sizes, int n_in,
                              void* d_out, int out_size)
{
    const float* x   = (const float*)d_in[0];
    const float* W_q = (const float*)d_in[1];
    const float* W_k = (const float*)d_in[2];
    const float* W_v = (const float*)d_in[3];
    const float* W_o = (const float*)d_in[4];
    float* out = (float*)d_out;

    __half *qkv_ptr = nullptr, *att_ptr = nullptr, *xh_ptr = nullptr, *wh_ptr = nullptr;
    cudaGetSymbolAddress((void**)&qkv_ptr, g_qkv);
    cudaGetSymbolAddress((void**)&att_ptr, g_att);
    cudaGetSymbolAddress((void**)&xh_ptr,  g_xh);
    cudaGetSymbolAddress((void**)&wh_ptr,  g_wh);

    cudaFuncSetAttribute((const void*)gemm_h2<true>,
                         cudaFuncAttributeMaxDynamicSharedMemorySize, GEMM_SMEM);
    cudaFuncSetAttribute((const void*)gemm_h2<false>,
                         cudaFuncAttributeMaxDynamicSharedMemorySize, GEMM_SMEM);
    cudaFuncSetAttribute((const void*)attn_h,
                         cudaFuncAttributeMaxDynamicSharedMemorySize, ATTN_SMEM);

    /* 0) fp32 -> fp16 operand staging */
    cvt_x<<<(M_ * D_ / 4) / 256, 256>>>(x, xh_ptr);
    cvt_w<<<(4 * D_ * D_ / 4) / 256, 256>>>(W_q, W_k, W_v, W_o, wh_ptr);

    /* 1) QKV projection: g_qkv[8192,3072](h) = xh @ [Wq|Wk|Wv]^T */
    {
        dim3 grid(N3_ / 128, M_ / 128);
        gemm_h2<true><<<grid, 256, GEMM_SMEM>>>(xh_ptr, wh_ptr, qkv_ptr, N3_);
    }

    /* 2) flash attention (fp16 mma, cp.async) -> g_att[8192,1024](h) */
    {
        dim3 grid(S_ / 128, B_ * H_);
        attn_h<<<grid, 256, ATTN_SMEM>>>();
    }

    /* 3) output projection: out(f32) = g_att @ Wo^T */
    {
        dim3 grid(D_ / 128, M_ / 128);
        gemm_h2<false><<<grid, 256, GEMM_SMEM>>>(att_ptr,
                                                 wh_ptr + (size_t)3 * D_ * D_,
                                                 out, D_);
    }
}